// round 8
// baseline (speedup 1.0000x reference)
#include <cuda_runtime.h>
#include <math.h>
#include <stdint.h>

// ---------------- problem constants ----------------
#define B_SZ   2
#define SEQL   2048
#define DM     2048
#define DI     4096
#define DS     128
#define HD     64
#define NH     64
#define CH     256
#define NC     8
#define CONV_DIM 4352           // DI + 2*DS
#define DPROJ    8512           // 2*DI + 2*DS + NH
#define EPSV   1e-5f
#define BL     (B_SZ * SEQL)    // 4096 rows

// ---------------- device scratch (static, no cudaMalloc) ----------------
__device__ float g_zxbcdt[(size_t)BL * DPROJ];     // in_proj output
__device__ float g_conv  [(size_t)BL * CONV_DIM];  // conv+silu output
__device__ float g_dt    [BL * NH];                // softplus(dt)
__device__ float g_acs   [B_SZ * NH * NC * CH];    // per-chunk cumsum(dA)
__device__ float g_states[B_SZ * NC * NH * HD * DS];
__device__ float g_prev  [B_SZ * NC * NH * HD * DS];
__device__ float g_y     [(size_t)BL * DI];        // Y then normalized y

extern __shared__ char dyn_smem[];   // used by y_kernel only

// ===== TF32 tensor-core GEMM: 3xTF32, pre-split smem, double-buffered =====
// C[M,N] = A[M,K] * Bw[N,K]^T.  fp32 in/out, fp32-level accuracy.
// Block tile 128x128, K-step 8, 2 smem stages of interleaved (hi,lo) float2.
// 256 threads (8 warps, 2x4 -> 64x32 warp tile), 2 CTAs/SM.

__device__ __forceinline__ void mma_tf32(float c[4], const uint32_t a[4],
                                         const uint32_t b[2])
{
    asm volatile(
        "mma.sync.aligned.m16n8k8.row.col.f32.tf32.tf32.f32 "
        "{%0,%1,%2,%3}, {%4,%5,%6,%7}, {%8,%9}, {%0,%1,%2,%3};\n"
        : "+f"(c[0]), "+f"(c[1]), "+f"(c[2]), "+f"(c[3])
        : "r"(a[0]), "r"(a[1]), "r"(a[2]), "r"(a[3]),
          "r"(b[0]), "r"(b[1]));
}

__device__ __forceinline__ float2 tf32_split2(float x)
{
    float hi = __uint_as_float(__float_as_uint(x) & 0xFFFFE000u);
    return make_float2(hi, x - hi);
}

#define KS    8    // K-step
#define PSTR  12   // smem row stride in float2: (12g+tig) mod 16 distinct per half-warp

__global__ void __launch_bounds__(256, 2) gemm_tf32_tn(const float* __restrict__ A,
                                                       const float* __restrict__ Bw,
                                                       float* __restrict__ C,
                                                       int M, int N, int K)
{
    __shared__ float2 As2[2][128][PSTR];   // 24576 B
    __shared__ float2 Bs2[2][128][PSTR];   // 24576 B   (total 49152 = 48KB)

    const int tid  = threadIdx.x;
    const int warp = tid >> 5;
    const int lane = tid & 31;
    const int g    = lane >> 2;      // 0..7
    const int tig  = lane & 3;       // 0..3
    const int wm   = warp >> 2;      // 0..1  -> 64-row slab
    const int wn   = warp & 3;       // 0..3  -> 32-col slab

    const int mBase = blockIdx.y * 128;
    const int nBase = blockIdx.x * 128;

    // GLD mapping: 128 rows x 8 cols per matrix -> 1 float4 per thread per matrix
    const int rL = tid >> 1;         // 0..127
    const int cc = (tid & 1) * 4;    // 0 or 4

    float acc[4][4][4];
#pragma unroll
    for (int mt = 0; mt < 4; mt++)
#pragma unroll
        for (int nt = 0; nt < 4; nt++)
#pragma unroll
            for (int e = 0; e < 4; e++) acc[mt][nt][e] = 0.f;

    const float* aP = A  + (size_t)(mBase + rL) * K + cc;
    const int    gn = nBase + rL;
    const float* bP = Bw + (size_t)gn * K + cc;
    const bool   ok = (gn < N);
    const float4 z4 = make_float4(0.f, 0.f, 0.f, 0.f);

    // split 4 floats -> two float4 of (hi,lo,hi,lo) and store
    auto store_split = [&](float2* dst, float4 v) {
        float2 s0 = tf32_split2(v.x), s1 = tf32_split2(v.y);
        float2 s2 = tf32_split2(v.z), s3 = tf32_split2(v.w);
        float4* d = reinterpret_cast<float4*>(dst);
        d[0] = make_float4(s0.x, s0.y, s1.x, s1.y);
        d[1] = make_float4(s2.x, s2.y, s3.x, s3.y);
    };

    // prologue: stage 0
    {
        float4 av = *reinterpret_cast<const float4*>(aP);
        float4 bv = ok ? *reinterpret_cast<const float4*>(bP) : z4;
        store_split(&As2[0][rL][cc], av);
        store_split(&Bs2[0][rL][cc], bv);
    }
    __syncthreads();

    const int nk = K / KS;
    for (int kt = 0; kt < nk; kt++) {
        const int cur  = kt & 1;
        const bool more = (kt + 1 < nk);
        float4 na, nb;
        if (more) {
            const int kc = (kt + 1) * KS;
            na = *reinterpret_cast<const float4*>(aP + kc);
            nb = ok ? *reinterpret_cast<const float4*>(bP + kc) : z4;
        }

        // fragments + 48 HMMA on stage `cur` (k = 0..7)
        uint32_t bh[4][2], bl[4][2];
#pragma unroll
        for (int nt = 0; nt < 4; nt++) {
            const int n = wn * 32 + nt * 8 + g;
            float2 b0 = Bs2[cur][n][tig];
            float2 b1 = Bs2[cur][n][tig + 4];
            bh[nt][0] = __float_as_uint(b0.x); bl[nt][0] = __float_as_uint(b0.y);
            bh[nt][1] = __float_as_uint(b1.x); bl[nt][1] = __float_as_uint(b1.y);
        }
#pragma unroll
        for (int mt = 0; mt < 4; mt++) {
            const int m0 = wm * 64 + mt * 16 + g;
            float2 A00 = As2[cur][m0][tig];
            float2 A10 = As2[cur][m0 + 8][tig];
            float2 A01 = As2[cur][m0][tig + 4];
            float2 A11 = As2[cur][m0 + 8][tig + 4];
            uint32_t ah[4] = { __float_as_uint(A00.x), __float_as_uint(A10.x),
                               __float_as_uint(A01.x), __float_as_uint(A11.x) };
            uint32_t al[4] = { __float_as_uint(A00.y), __float_as_uint(A10.y),
                               __float_as_uint(A01.y), __float_as_uint(A11.y) };
#pragma unroll
            for (int nt = 0; nt < 4; nt++) {
                mma_tf32(acc[mt][nt], ah, bh[nt]);   // hi*hi
                mma_tf32(acc[mt][nt], ah, bl[nt]);   // hi*lo
                mma_tf32(acc[mt][nt], al, bh[nt]);   // lo*hi
            }
        }

        if (more) {
            const int nxt = cur ^ 1;
            store_split(&As2[nxt][rL][cc], na);
            store_split(&Bs2[nxt][rL][cc], nb);
        }
        __syncthreads();
    }

    // epilogue
#pragma unroll
    for (int mt = 0; mt < 4; mt++) {
        const int row0 = mBase + wm * 64 + mt * 16 + g;
#pragma unroll
        for (int nt = 0; nt < 4; nt++) {
            const int col = nBase + wn * 32 + nt * 8 + 2 * tig;
            if (col < N) {
                float2 v01 = make_float2(acc[mt][nt][0], acc[mt][nt][1]);
                float2 v23 = make_float2(acc[mt][nt][2], acc[mt][nt][3]);
                *reinterpret_cast<float2*>(&C[(size_t)row0 * N + col])       = v01;
                *reinterpret_cast<float2*>(&C[(size_t)(row0 + 8) * N + col]) = v23;
            }
        }
    }
}

// ---------------- depthwise causal conv (width 4) + bias + silu ----------------
__global__ void conv_silu_kernel(const float* __restrict__ conv_w,
                                 const float* __restrict__ conv_b)
{
    int idx = blockIdx.x * blockDim.x + threadIdx.x;
    if (idx >= BL * CONV_DIM) return;
    int ch = idx % CONV_DIM;
    int l  = (idx / CONV_DIM) % SEQL;
    int b  = idx / (CONV_DIM * SEQL);
    float acc = conv_b[ch];
#pragma unroll
    for (int j = 0; j < 4; j++) {
        int t = l - 3 + j;
        if (t >= 0)
            acc = fmaf(conv_w[ch * 4 + j],
                       g_zxbcdt[(size_t)(b * SEQL + t) * DPROJ + DI + ch], acc);
    }
    g_conv[(size_t)(b * SEQL + l) * CONV_DIM + ch] = acc / (1.f + expf(-acc));
}

// ---------------- dt = softplus(raw + dt_bias) ----------------
__global__ void dt_kernel(const float* __restrict__ dt_bias)
{
    int idx = blockIdx.x * blockDim.x + threadIdx.x;
    if (idx >= BL * NH) return;
    int hh  = idx % NH;
    int row = idx / NH;
    float v = g_zxbcdt[(size_t)row * DPROJ + DI + CONV_DIM + hh] + dt_bias[hh];
    g_dt[idx] = (v > 20.f) ? v : log1pf(expf(v));
}

// ---------------- per-chunk inclusive cumsum of dA = dt * A ----------------
__global__ void scan_kernel(const float* __restrict__ A_log)
{
    const int bc = blockIdx.x;          // ((b*NH + h)*NC + c)
    const int c  = bc % NC;
    const int h  = (bc / NC) % NH;
    const int b  = bc / (NC * NH);
    const int l  = threadIdx.x;
    const float A = -expf(A_log[h]);
    float v = g_dt[(size_t)(b * SEQL + c * CH + l) * NH + h] * A;
    __shared__ float s[CH];
    s[l] = v;
    __syncthreads();
    for (int off = 1; off < CH; off <<= 1) {
        float t = (l >= off) ? s[l - off] : 0.f;
        __syncthreads();
        s[l] += t;
        __syncthreads();
    }
    g_acs[(size_t)bc * CH + l] = s[l];
}

// ---------------- per-chunk states ----------------
__global__ void __launch_bounds__(256) states_kernel()
{
    __shared__ float Bs[32][129];
    __shared__ float Xs[32][65];
    const int tid = threadIdx.x;
    const int tx  = tid & 15;
    const int ty  = tid >> 4;
    const int h = blockIdx.x % NH;
    const int c = (blockIdx.x / NH) % NC;
    const int b = blockIdx.x / (NH * NC);
    const size_t rowBase = (size_t)(b * SEQL + c * CH);
    const size_t acsBase = ((size_t)(b * NH + h) * NC + c) * CH;
    const float acsLast = g_acs[acsBase + CH - 1];

    float acc[4][8];
#pragma unroll
    for (int i = 0; i < 4; i++)
#pragma unroll
        for (int j = 0; j < 8; j++) acc[i][j] = 0.f;

    for (int s0 = 0; s0 < CH; s0 += 32) {
        __syncthreads();
#pragma unroll
        for (int it = 0; it < 4; it++) {
            int slot = tid + it * 256;
            int sr = slot >> 5;
            int n4 = (slot & 31) * 4;
            float4 v = *reinterpret_cast<const float4*>(
                &g_conv[(rowBase + s0 + sr) * CONV_DIM + DI + n4]);
            Bs[sr][n4 + 0] = v.x; Bs[sr][n4 + 1] = v.y;
            Bs[sr][n4 + 2] = v.z; Bs[sr][n4 + 3] = v.w;
        }
#pragma unroll
        for (int it = 0; it < 2; it++) {
            int slot = tid + it * 256;
            int sr = slot >> 4;
            int p4 = (slot & 15) * 4;
            size_t row = rowBase + s0 + sr;
            float sc = g_dt[row * NH + h] * expf(acsLast - g_acs[acsBase + s0 + sr]);
            float4 v = *reinterpret_cast<const float4*>(&g_conv[row * CONV_DIM + h * HD + p4]);
            Xs[sr][p4 + 0] = v.x * sc; Xs[sr][p4 + 1] = v.y * sc;
            Xs[sr][p4 + 2] = v.z * sc; Xs[sr][p4 + 3] = v.w * sc;
        }
        __syncthreads();
#pragma unroll 8
        for (int s = 0; s < 32; s++) {
            float a[4], bb[8];
#pragma unroll
            for (int i = 0; i < 4; i++) a[i] = Xs[s][ty * 4 + i];
#pragma unroll
            for (int j = 0; j < 4; j++) {
                bb[j]     = Bs[s][tx * 4 + j];
                bb[4 + j] = Bs[s][64 + tx * 4 + j];
            }
#pragma unroll
            for (int i = 0; i < 4; i++)
#pragma unroll
                for (int j = 0; j < 8; j++)
                    acc[i][j] = fmaf(a[i], bb[j], acc[i][j]);
        }
    }
    const size_t base = ((size_t)(b * NC + c) * NH + h) * (HD * DS);
#pragma unroll
    for (int i = 0; i < 4; i++) {
        int p = ty * 4 + i;
#pragma unroll
        for (int j = 0; j < 8; j++) {
            int n = (j < 4) ? (tx * 4 + j) : (64 + tx * 4 + j - 4);
            g_states[base + (size_t)p * DS + n] = acc[i][j];
        }
    }
}

// ---------------- inter-chunk recurrence ----------------
__global__ void chunk_rec_kernel()
{
    int idx = blockIdx.x * blockDim.x + threadIdx.x;
    if (idx >= B_SZ * NH * HD * DS) return;
    int n = idx % DS;
    int p = (idx / DS) % HD;
    int h = (idx / (DS * HD)) % NH;
    int b = idx / (DS * HD * NH);
    float prev = 0.f;
#pragma unroll
    for (int c = 0; c < NC; c++) {
        size_t off = (((size_t)(b * NC + c) * NH + h) * HD + p) * DS + n;
        g_prev[off] = prev;
        float cs = g_acs[((size_t)(b * NH + h) * NC + c) * CH + CH - 1];
        prev = expf(cs) * prev + g_states[off];
    }
}

// ---------------- SSD core ----------------
struct YS {
    float Cn [DS][129];
    float Bn [DS][33];
    float Pt [32][129];
    float Xd [32][65];
    float Pvn[DS][65];
    float acsl[128];
    float acss[32];
};

__global__ void __launch_bounds__(256) y_kernel(const float* __restrict__ Dvec)
{
    YS& S = *reinterpret_cast<YS*>(dyn_smem);
    const int tid = threadIdx.x;
    const int h  = blockIdx.x % NH;
    const int c  = (blockIdx.x / NH) % NC;
    const int b  = blockIdx.x / (NH * NC);
    const int lt = blockIdx.y;
    const size_t rowBase = (size_t)(b * SEQL + c * CH);
    const size_t acsBase = ((size_t)(b * NH + h) * NC + c) * CH;
    const int ly = tid >> 3;
    const int px = tid & 7;

#pragma unroll
    for (int it = 0; it < 16; it++) {
        int slot = tid + it * 256;
        int l  = slot >> 5;
        int n4 = (slot & 31) * 4;
        float4 v = *reinterpret_cast<const float4*>(
            &g_conv[(rowBase + lt * 128 + l) * CONV_DIM + DI + DS + n4]);
        S.Cn[n4 + 0][l] = v.x; S.Cn[n4 + 1][l] = v.y;
        S.Cn[n4 + 2][l] = v.z; S.Cn[n4 + 3][l] = v.w;
    }
    if (tid < 128) S.acsl[tid] = g_acs[acsBase + lt * 128 + tid];
    const size_t pvBase = ((size_t)(b * NC + c) * NH + h) * (HD * DS);
#pragma unroll
    for (int it = 0; it < 8; it++) {
        int slot = tid + it * 256;
        int p  = slot >> 5;
        int n4 = (slot & 31) * 4;
        float4 v = *reinterpret_cast<const float4*>(&g_prev[pvBase + (size_t)p * DS + n4]);
        S.Pvn[n4 + 0][p] = v.x; S.Pvn[n4 + 1][p] = v.y;
        S.Pvn[n4 + 2][p] = v.z; S.Pvn[n4 + 3][p] = v.w;
    }

    float yacc[4][8];
#pragma unroll
    for (int i = 0; i < 4; i++)
#pragma unroll
        for (int j = 0; j < 8; j++) yacc[i][j] = 0.f;

    const int nst = 4 * (lt + 1);
    for (int st = 0; st < nst; st++) {
        const int s0 = st * 32;
        __syncthreads();
#pragma unroll
        for (int it = 0; it < 4; it++) {
            int slot = tid + it * 256;
            int sr = slot >> 5;
            int n4 = (slot & 31) * 4;
            float4 v = *reinterpret_cast<const float4*>(
                &g_conv[(rowBase + s0 + sr) * CONV_DIM + DI + n4]);
            S.Bn[n4 + 0][sr] = v.x; S.Bn[n4 + 1][sr] = v.y;
            S.Bn[n4 + 2][sr] = v.z; S.Bn[n4 + 3][sr] = v.w;
        }
#pragma unroll
        for (int it = 0; it < 2; it++) {
            int slot = tid + it * 256;
            int sr = slot >> 4;
            int p4 = (slot & 15) * 4;
            size_t row = rowBase + s0 + sr;
            float dt = g_dt[row * NH + h];
            float4 v = *reinterpret_cast<const float4*>(&g_conv[row * CONV_DIM + h * HD + p4]);
            S.Xd[sr][p4 + 0] = v.x * dt; S.Xd[sr][p4 + 1] = v.y * dt;
            S.Xd[sr][p4 + 2] = v.z * dt; S.Xd[sr][p4 + 3] = v.w * dt;
        }
        if (tid < 32) S.acss[tid] = g_acs[acsBase + s0 + tid];
        __syncthreads();

        float sa[4][4];
#pragma unroll
        for (int i = 0; i < 4; i++)
#pragma unroll
            for (int j = 0; j < 4; j++) sa[i][j] = 0.f;
#pragma unroll 4
        for (int n = 0; n < DS; n++) {
            float a[4], bb[4];
#pragma unroll
            for (int i = 0; i < 4; i++) a[i]  = S.Cn[n][ly * 4 + i];
#pragma unroll
            for (int j = 0; j < 4; j++) bb[j] = S.Bn[n][px * 4 + j];
#pragma unroll
            for (int i = 0; i < 4; i++)
#pragma unroll
                for (int j = 0; j < 4; j++)
                    sa[i][j] = fmaf(a[i], bb[j], sa[i][j]);
        }
#pragma unroll
        for (int i = 0; i < 4; i++) {
            int l  = ly * 4 + i;
            int lg = lt * 128 + l;
            float al = S.acsl[l];
#pragma unroll
            for (int j = 0; j < 4; j++) {
                int sl = px * 4 + j;
                int sg = s0 + sl;
                float w = (sg <= lg) ? expf(al - S.acss[sl]) * sa[i][j] : 0.f;
                S.Pt[sl][l] = w;
            }
        }
        __syncthreads();
#pragma unroll 8
        for (int s = 0; s < 32; s++) {
            float a[4], bb[8];
#pragma unroll
            for (int i = 0; i < 4; i++) a[i] = S.Pt[s][ly * 4 + i];
#pragma unroll
            for (int j = 0; j < 4; j++) {
                bb[j]     = S.Xd[s][px * 4 + j];
                bb[4 + j] = S.Xd[s][32 + px * 4 + j];
            }
#pragma unroll
            for (int i = 0; i < 4; i++)
#pragma unroll
                for (int j = 0; j < 8; j++)
                    yacc[i][j] = fmaf(a[i], bb[j], yacc[i][j]);
        }
    }

    float oacc[4][8];
#pragma unroll
    for (int i = 0; i < 4; i++)
#pragma unroll
        for (int j = 0; j < 8; j++) oacc[i][j] = 0.f;
#pragma unroll 4
    for (int n = 0; n < DS; n++) {
        float a[4], bb[8];
#pragma unroll
        for (int i = 0; i < 4; i++) a[i] = S.Cn[n][ly * 4 + i];
#pragma unroll
        for (int j = 0; j < 4; j++) {
            bb[j]     = S.Pvn[n][px * 4 + j];
            bb[4 + j] = S.Pvn[n][32 + px * 4 + j];
        }
#pragma unroll
        for (int i = 0; i < 4; i++)
#pragma unroll
            for (int j = 0; j < 8; j++)
                oacc[i][j] = fmaf(a[i], bb[j], oacc[i][j]);
    }

    const float Dh = Dvec[h];
#pragma unroll
    for (int i = 0; i < 4; i++) {
        int l = ly * 4 + i;
        size_t row = rowBase + lt * 128 + l;
        float el = expf(S.acsl[l]);
#pragma unroll
        for (int j = 0; j < 8; j++) {
            int p = (j < 4) ? (px * 4 + j) : (32 + px * 4 + j - 4);
            float xs = g_conv[row * CONV_DIM + h * HD + p];
            g_y[row * DI + h * HD + p] = yacc[i][j] + el * oacc[i][j] + Dh * xs;
        }
    }
}

// ---------------- gate with silu(z) + RMSNorm ----------------
__global__ void __launch_bounds__(256) gate_norm_kernel(const float* __restrict__ norm_w)
{
    const int row = blockIdx.x;
    const float* yrow = &g_y[(size_t)row * DI];
    const float* zrow = &g_zxbcdt[(size_t)row * DPROJ];
    float vals[16];
    float ss = 0.f;
#pragma unroll
    for (int it = 0; it < 16; it++) {
        int i = threadIdx.x + it * 256;
        float z  = zrow[i];
        float yg = yrow[i] * (z / (1.f + expf(-z)));
        vals[it] = yg;
        ss = fmaf(yg, yg, ss);
    }
    __shared__ float red[8];
#pragma unroll
    for (int o = 16; o > 0; o >>= 1) ss += __shfl_xor_sync(0xffffffffu, ss, o);
    if ((threadIdx.x & 31) == 0) red[threadIdx.x >> 5] = ss;
    __syncthreads();
    float tot = 0.f;
#pragma unroll
    for (int w = 0; w < 8; w++) tot += red[w];
    float scale = rsqrtf(tot / (float)DI + EPSV);
    float* yw = &g_y[(size_t)row * DI];
#pragma unroll
    for (int it = 0; it < 16; it++) {
        int i = threadIdx.x + it * 256;
        yw[i] = vals[it] * scale * norm_w[i];
    }
}

// ---------------- launch ----------------
extern "C" void kernel_launch(void* const* d_in, const int* in_sizes, int n_in,
                              void* d_out, int out_size)
{
    (void)in_sizes; (void)n_in; (void)out_size;
    const float* x        = (const float*)d_in[0];
    const float* in_proj  = (const float*)d_in[1];
    const float* conv_w   = (const float*)d_in[2];
    const float* conv_b   = (const float*)d_in[3];
    const float* dt_bias  = (const float*)d_in[4];
    const float* A_log    = (const float*)d_in[5];
    const float* Dv       = (const float*)d_in[6];
    const float* norm_w   = (const float*)d_in[7];
    const float* out_proj = (const float*)d_in[8];
    float* out = (float*)d_out;

    float* zx = nullptr;
    float* yb = nullptr;
    cudaGetSymbolAddress((void**)&zx, g_zxbcdt);
    cudaGetSymbolAddress((void**)&yb, g_y);

    cudaFuncSetAttribute(y_kernel, cudaFuncAttributeMaxDynamicSharedMemorySize,
                         (int)sizeof(YS));

    // 1. in_proj GEMM (3xTF32, pre-split, double-buffered)
    gemm_tf32_tn<<<dim3((DPROJ + 127) / 128, BL / 128), 256>>>(x, in_proj, zx, BL, DPROJ, DM);
    // 2. depthwise conv + silu
    conv_silu_kernel<<<(BL * CONV_DIM + 255) / 256, 256>>>(conv_w, conv_b);
    // 3. dt = softplus
    dt_kernel<<<(BL * NH + 255) / 256, 256>>>(dt_bias);
    // 4. per-chunk cumsum of dA
    scan_kernel<<<B_SZ * NH * NC, CH>>>(A_log);
    // 5. per-chunk states
    states_kernel<<<B_SZ * NC * NH, 256>>>();
    // 6. inter-chunk recurrence
    chunk_rec_kernel<<<(B_SZ * NH * HD * DS + 255) / 256, 256>>>();
    // 7. SSD core -> Y
    y_kernel<<<dim3(B_SZ * NC * NH, 2), 256, sizeof(YS)>>>(Dv);
    // 8. gate + RMSNorm
    gate_norm_kernel<<<BL, 256>>>(norm_w);
    // 9. out_proj GEMM (3xTF32, pre-split, double-buffered)
    gemm_tf32_tn<<<dim3(DM / 128, BL / 128), 256>>>(yb, out_proj, out, BL, DM, DI);
}

// round 9
// speedup vs baseline: 1.5080x; 1.5080x over previous
#include <cuda_runtime.h>
#include <cuda_bf16.h>
#include <math.h>
#include <stdint.h>

// ---------------- problem constants ----------------
#define B_SZ   2
#define SEQL   2048
#define DM     2048
#define DI     4096
#define DS     128
#define HD     64
#define NH     64
#define CH     256
#define NC     8
#define CONV_DIM 4352           // DI + 2*DS
#define DPROJ    8512           // 2*DI + 2*DS + NH
#define EPSV   1e-5f
#define BL     (B_SZ * SEQL)    // 4096 rows

// ---------------- device scratch (static, no cudaMalloc) ----------------
__device__ float g_zxbcdt[(size_t)BL * DPROJ];     // in_proj output
__device__ float g_conv  [(size_t)BL * CONV_DIM];  // conv+silu output
__device__ float g_dt    [BL * NH];                // softplus(dt)
__device__ float g_acs   [B_SZ * NH * NC * CH];    // per-chunk cumsum(dA)
__device__ float g_states[B_SZ * NC * NH * HD * DS];
__device__ float g_prev  [B_SZ * NC * NH * HD * DS];
__device__ float g_y     [(size_t)BL * DI];        // Y then normalized y

extern __shared__ char dyn_smem[];   // used by y_kernel only

// ===== bf16x3 tensor-core GEMM (hi/lo split, m16n8k16, double-buffered) =====
// C[M,N] = A[M,K] * Bw[N,K]^T.  fp32 in/out, ~fp32 accuracy via
// x = hi + lo (both bf16), C += hi*hi + hi*lo + lo*hi (fp32 accum).
// Block tile 128x128, K-step 16, 2 smem stages, 1 sync per step.
// 256 threads (8 warps, 2x4 -> 64x32 warp tile), 2 CTAs/SM, 48KB static smem.

__device__ __forceinline__ void mma_bf16(float c[4], const uint32_t a[4],
                                         const uint32_t b[2])
{
    asm volatile(
        "mma.sync.aligned.m16n8k16.row.col.f32.bf16.bf16.f32 "
        "{%0,%1,%2,%3}, {%4,%5,%6,%7}, {%8,%9}, {%0,%1,%2,%3};\n"
        : "+f"(c[0]), "+f"(c[1]), "+f"(c[2]), "+f"(c[3])
        : "r"(a[0]), "r"(a[1]), "r"(a[2]), "r"(a[3]),
          "r"(b[0]), "r"(b[1]));
}

// split pair (x,y) -> packed bf16x2 hi plane + packed bf16x2 residual plane
__device__ __forceinline__ uint2 split_pack2(float x, float y)
{
    __nv_bfloat162 h = __floats2bfloat162_rn(x, y);
    float rx = x - __low2float(h);
    float ry = y - __high2float(h);
    __nv_bfloat162 l = __floats2bfloat162_rn(rx, ry);
    uint2 r;
    r.x = *reinterpret_cast<uint32_t*>(&h);
    r.y = *reinterpret_cast<uint32_t*>(&l);
    return r;
}

#define KSB   16   // K-step (one m16n8k16 per tile step)
#define QSTR  12   // smem row stride in uint2 (k-pairs): (12g+tig) mod 16 conflict-free

__global__ void __launch_bounds__(256, 2) gemm_bf16x3_tn(const float* __restrict__ A,
                                                         const float* __restrict__ Bw,
                                                         float* __restrict__ C,
                                                         int M, int N, int K)
{
    // element [r][p] = (hi_bf16x2, lo_bf16x2) for k = 2p, 2p+1   (p = 0..7)
    __shared__ uint2 As2[2][128][QSTR];   // 12288 B per stage
    __shared__ uint2 Bs2[2][128][QSTR];   // total 49152 B = 48 KB

    const int tid  = threadIdx.x;
    const int warp = tid >> 5;
    const int lane = tid & 31;
    const int g    = lane >> 2;      // 0..7
    const int tig  = lane & 3;       // 0..3
    const int wm   = warp >> 2;      // 0..1  -> 64-row slab
    const int wn   = warp & 3;       // 0..3  -> 32-col slab

    const int mBase = blockIdx.y * 128;
    const int nBase = blockIdx.x * 128;

    // GLD mapping: 128 rows x 16 floats per matrix; thread covers 8 floats
    const int rL = tid >> 1;         // 0..127
    const int hb = (tid & 1) * 8;    // k offset 0 or 8
    const int pb = hb >> 1;          // pair base 0 or 4

    float acc[4][4][4];
#pragma unroll
    for (int mt = 0; mt < 4; mt++)
#pragma unroll
        for (int nt = 0; nt < 4; nt++)
#pragma unroll
            for (int e = 0; e < 4; e++) acc[mt][nt][e] = 0.f;

    const float* aP = A  + (size_t)(mBase + rL) * K + hb;
    const int    gn = nBase + rL;
    const float* bP = Bw + (size_t)gn * K + hb;
    const bool   ok = (gn < N);
    const float4 z4 = make_float4(0.f, 0.f, 0.f, 0.f);

    auto store8 = [&](uint2 (*dst)[QSTR], float4 v0, float4 v1) {
        dst[rL][pb + 0] = split_pack2(v0.x, v0.y);
        dst[rL][pb + 1] = split_pack2(v0.z, v0.w);
        dst[rL][pb + 2] = split_pack2(v1.x, v1.y);
        dst[rL][pb + 3] = split_pack2(v1.z, v1.w);
    };

    // prologue: stage 0
    {
        float4 a0 = *reinterpret_cast<const float4*>(aP);
        float4 a1 = *reinterpret_cast<const float4*>(aP + 4);
        float4 b0 = ok ? *reinterpret_cast<const float4*>(bP)     : z4;
        float4 b1 = ok ? *reinterpret_cast<const float4*>(bP + 4) : z4;
        store8(As2[0], a0, a1);
        store8(Bs2[0], b0, b1);
    }
    __syncthreads();

    const int nk = K / KSB;
    for (int kt = 0; kt < nk; kt++) {
        const int cur  = kt & 1;
        const bool more = (kt + 1 < nk);
        float4 na0, na1, nb0, nb1;
        if (more) {
            const int kc = (kt + 1) * KSB;
            na0 = *reinterpret_cast<const float4*>(aP + kc);
            na1 = *reinterpret_cast<const float4*>(aP + kc + 4);
            nb0 = ok ? *reinterpret_cast<const float4*>(bP + kc)     : z4;
            nb1 = ok ? *reinterpret_cast<const float4*>(bP + kc + 4) : z4;
        }

        // fragments + 48 HMMA.k16 on stage `cur`
        uint32_t bh[4][2], bl[4][2];
#pragma unroll
        for (int nt = 0; nt < 4; nt++) {
            const int n = wn * 32 + nt * 8 + g;
            uint2 q0 = Bs2[cur][n][tig];        // k pair tig   (k = 2tig..)
            uint2 q1 = Bs2[cur][n][tig + 4];    // k pair tig+4 (k = 8+2tig..)
            bh[nt][0] = q0.x; bl[nt][0] = q0.y;
            bh[nt][1] = q1.x; bl[nt][1] = q1.y;
        }
#pragma unroll
        for (int mt = 0; mt < 4; mt++) {
            const int m0 = wm * 64 + mt * 16 + g;
            uint2 p00 = As2[cur][m0][tig];          // a0: row g,   k pair tig
            uint2 p10 = As2[cur][m0 + 8][tig];      // a1: row g+8, k pair tig
            uint2 p01 = As2[cur][m0][tig + 4];      // a2: row g,   k pair tig+4
            uint2 p11 = As2[cur][m0 + 8][tig + 4];  // a3: row g+8, k pair tig+4
            uint32_t ah[4] = { p00.x, p10.x, p01.x, p11.x };
            uint32_t al[4] = { p00.y, p10.y, p01.y, p11.y };
#pragma unroll
            for (int nt = 0; nt < 4; nt++) {
                mma_bf16(acc[mt][nt], ah, bh[nt]);   // hi*hi
                mma_bf16(acc[mt][nt], ah, bl[nt]);   // hi*lo
                mma_bf16(acc[mt][nt], al, bh[nt]);   // lo*hi
            }
        }

        if (more) {
            const int nxt = cur ^ 1;
            store8(As2[nxt], na0, na1);
            store8(Bs2[nxt], nb0, nb1);
        }
        __syncthreads();
    }

    // epilogue (same accumulator layout as m16n8k8)
#pragma unroll
    for (int mt = 0; mt < 4; mt++) {
        const int row0 = mBase + wm * 64 + mt * 16 + g;
#pragma unroll
        for (int nt = 0; nt < 4; nt++) {
            const int col = nBase + wn * 32 + nt * 8 + 2 * tig;
            if (col < N) {
                float2 v01 = make_float2(acc[mt][nt][0], acc[mt][nt][1]);
                float2 v23 = make_float2(acc[mt][nt][2], acc[mt][nt][3]);
                *reinterpret_cast<float2*>(&C[(size_t)row0 * N + col])       = v01;
                *reinterpret_cast<float2*>(&C[(size_t)(row0 + 8) * N + col]) = v23;
            }
        }
    }
}

// ---------------- depthwise causal conv (width 4) + bias + silu ----------------
__global__ void conv_silu_kernel(const float* __restrict__ conv_w,
                                 const float* __restrict__ conv_b)
{
    int idx = blockIdx.x * blockDim.x + threadIdx.x;
    if (idx >= BL * CONV_DIM) return;
    int ch = idx % CONV_DIM;
    int l  = (idx / CONV_DIM) % SEQL;
    int b  = idx / (CONV_DIM * SEQL);
    float acc = conv_b[ch];
#pragma unroll
    for (int j = 0; j < 4; j++) {
        int t = l - 3 + j;
        if (t >= 0)
            acc = fmaf(conv_w[ch * 4 + j],
                       g_zxbcdt[(size_t)(b * SEQL + t) * DPROJ + DI + ch], acc);
    }
    g_conv[(size_t)(b * SEQL + l) * CONV_DIM + ch] = acc / (1.f + expf(-acc));
}

// ---------------- dt = softplus(raw + dt_bias) ----------------
__global__ void dt_kernel(const float* __restrict__ dt_bias)
{
    int idx = blockIdx.x * blockDim.x + threadIdx.x;
    if (idx >= BL * NH) return;
    int hh  = idx % NH;
    int row = idx / NH;
    float v = g_zxbcdt[(size_t)row * DPROJ + DI + CONV_DIM + hh] + dt_bias[hh];
    g_dt[idx] = (v > 20.f) ? v : log1pf(expf(v));
}

// ---------------- per-chunk inclusive cumsum of dA = dt * A ----------------
__global__ void scan_kernel(const float* __restrict__ A_log)
{
    const int bc = blockIdx.x;          // ((b*NH + h)*NC + c)
    const int c  = bc % NC;
    const int h  = (bc / NC) % NH;
    const int b  = bc / (NC * NH);
    const int l  = threadIdx.x;
    const float A = -expf(A_log[h]);
    float v = g_dt[(size_t)(b * SEQL + c * CH + l) * NH + h] * A;
    __shared__ float s[CH];
    s[l] = v;
    __syncthreads();
    for (int off = 1; off < CH; off <<= 1) {
        float t = (l >= off) ? s[l - off] : 0.f;
        __syncthreads();
        s[l] += t;
        __syncthreads();
    }
    g_acs[(size_t)bc * CH + l] = s[l];
}

// ---------------- per-chunk states ----------------
__global__ void __launch_bounds__(256) states_kernel()
{
    __shared__ float Bs[32][129];
    __shared__ float Xs[32][65];
    const int tid = threadIdx.x;
    const int tx  = tid & 15;
    const int ty  = tid >> 4;
    const int h = blockIdx.x % NH;
    const int c = (blockIdx.x / NH) % NC;
    const int b = blockIdx.x / (NH * NC);
    const size_t rowBase = (size_t)(b * SEQL + c * CH);
    const size_t acsBase = ((size_t)(b * NH + h) * NC + c) * CH;
    const float acsLast = g_acs[acsBase + CH - 1];

    float acc[4][8];
#pragma unroll
    for (int i = 0; i < 4; i++)
#pragma unroll
        for (int j = 0; j < 8; j++) acc[i][j] = 0.f;

    for (int s0 = 0; s0 < CH; s0 += 32) {
        __syncthreads();
#pragma unroll
        for (int it = 0; it < 4; it++) {
            int slot = tid + it * 256;
            int sr = slot >> 5;
            int n4 = (slot & 31) * 4;
            float4 v = *reinterpret_cast<const float4*>(
                &g_conv[(rowBase + s0 + sr) * CONV_DIM + DI + n4]);
            Bs[sr][n4 + 0] = v.x; Bs[sr][n4 + 1] = v.y;
            Bs[sr][n4 + 2] = v.z; Bs[sr][n4 + 3] = v.w;
        }
#pragma unroll
        for (int it = 0; it < 2; it++) {
            int slot = tid + it * 256;
            int sr = slot >> 4;
            int p4 = (slot & 15) * 4;
            size_t row = rowBase + s0 + sr;
            float sc = g_dt[row * NH + h] * expf(acsLast - g_acs[acsBase + s0 + sr]);
            float4 v = *reinterpret_cast<const float4*>(&g_conv[row * CONV_DIM + h * HD + p4]);
            Xs[sr][p4 + 0] = v.x * sc; Xs[sr][p4 + 1] = v.y * sc;
            Xs[sr][p4 + 2] = v.z * sc; Xs[sr][p4 + 3] = v.w * sc;
        }
        __syncthreads();
#pragma unroll 8
        for (int s = 0; s < 32; s++) {
            float a[4], bb[8];
#pragma unroll
            for (int i = 0; i < 4; i++) a[i] = Xs[s][ty * 4 + i];
#pragma unroll
            for (int j = 0; j < 4; j++) {
                bb[j]     = Bs[s][tx * 4 + j];
                bb[4 + j] = Bs[s][64 + tx * 4 + j];
            }
#pragma unroll
            for (int i = 0; i < 4; i++)
#pragma unroll
                for (int j = 0; j < 8; j++)
                    acc[i][j] = fmaf(a[i], bb[j], acc[i][j]);
        }
    }
    const size_t base = ((size_t)(b * NC + c) * NH + h) * (HD * DS);
#pragma unroll
    for (int i = 0; i < 4; i++) {
        int p = ty * 4 + i;
#pragma unroll
        for (int j = 0; j < 8; j++) {
            int n = (j < 4) ? (tx * 4 + j) : (64 + tx * 4 + j - 4);
            g_states[base + (size_t)p * DS + n] = acc[i][j];
        }
    }
}

// ---------------- inter-chunk recurrence ----------------
__global__ void chunk_rec_kernel()
{
    int idx = blockIdx.x * blockDim.x + threadIdx.x;
    if (idx >= B_SZ * NH * HD * DS) return;
    int n = idx % DS;
    int p = (idx / DS) % HD;
    int h = (idx / (DS * HD)) % NH;
    int b = idx / (DS * HD * NH);
    float prev = 0.f;
#pragma unroll
    for (int c = 0; c < NC; c++) {
        size_t off = (((size_t)(b * NC + c) * NH + h) * HD + p) * DS + n;
        g_prev[off] = prev;
        float cs = g_acs[((size_t)(b * NH + h) * NC + c) * CH + CH - 1];
        prev = expf(cs) * prev + g_states[off];
    }
}

// ---------------- SSD core ----------------
struct YS {
    float Cn [DS][129];
    float Bn [DS][33];
    float Pt [32][129];
    float Xd [32][65];
    float Pvn[DS][65];
    float acsl[128];
    float acss[32];
};

__global__ void __launch_bounds__(256) y_kernel(const float* __restrict__ Dvec)
{
    YS& S = *reinterpret_cast<YS*>(dyn_smem);
    const int tid = threadIdx.x;
    const int h  = blockIdx.x % NH;
    const int c  = (blockIdx.x / NH) % NC;
    const int b  = blockIdx.x / (NH * NC);
    const int lt = blockIdx.y;
    const size_t rowBase = (size_t)(b * SEQL + c * CH);
    const size_t acsBase = ((size_t)(b * NH + h) * NC + c) * CH;
    const int ly = tid >> 3;
    const int px = tid & 7;

#pragma unroll
    for (int it = 0; it < 16; it++) {
        int slot = tid + it * 256;
        int l  = slot >> 5;
        int n4 = (slot & 31) * 4;
        float4 v = *reinterpret_cast<const float4*>(
            &g_conv[(rowBase + lt * 128 + l) * CONV_DIM + DI + DS + n4]);
        S.Cn[n4 + 0][l] = v.x; S.Cn[n4 + 1][l] = v.y;
        S.Cn[n4 + 2][l] = v.z; S.Cn[n4 + 3][l] = v.w;
    }
    if (tid < 128) S.acsl[tid] = g_acs[acsBase + lt * 128 + tid];
    const size_t pvBase = ((size_t)(b * NC + c) * NH + h) * (HD * DS);
#pragma unroll
    for (int it = 0; it < 8; it++) {
        int slot = tid + it * 256;
        int p  = slot >> 5;
        int n4 = (slot & 31) * 4;
        float4 v = *reinterpret_cast<const float4*>(&g_prev[pvBase + (size_t)p * DS + n4]);
        S.Pvn[n4 + 0][p] = v.x; S.Pvn[n4 + 1][p] = v.y;
        S.Pvn[n4 + 2][p] = v.z; S.Pvn[n4 + 3][p] = v.w;
    }

    float yacc[4][8];
#pragma unroll
    for (int i = 0; i < 4; i++)
#pragma unroll
        for (int j = 0; j < 8; j++) yacc[i][j] = 0.f;

    const int nst = 4 * (lt + 1);
    for (int st = 0; st < nst; st++) {
        const int s0 = st * 32;
        __syncthreads();
#pragma unroll
        for (int it = 0; it < 4; it++) {
            int slot = tid + it * 256;
            int sr = slot >> 5;
            int n4 = (slot & 31) * 4;
            float4 v = *reinterpret_cast<const float4*>(
                &g_conv[(rowBase + s0 + sr) * CONV_DIM + DI + n4]);
            S.Bn[n4 + 0][sr] = v.x; S.Bn[n4 + 1][sr] = v.y;
            S.Bn[n4 + 2][sr] = v.z; S.Bn[n4 + 3][sr] = v.w;
        }
#pragma unroll
        for (int it = 0; it < 2; it++) {
            int slot = tid + it * 256;
            int sr = slot >> 4;
            int p4 = (slot & 15) * 4;
            size_t row = rowBase + s0 + sr;
            float dt = g_dt[row * NH + h];
            float4 v = *reinterpret_cast<const float4*>(&g_conv[row * CONV_DIM + h * HD + p4]);
            S.Xd[sr][p4 + 0] = v.x * dt; S.Xd[sr][p4 + 1] = v.y * dt;
            S.Xd[sr][p4 + 2] = v.z * dt; S.Xd[sr][p4 + 3] = v.w * dt;
        }
        if (tid < 32) S.acss[tid] = g_acs[acsBase + s0 + tid];
        __syncthreads();

        float sa[4][4];
#pragma unroll
        for (int i = 0; i < 4; i++)
#pragma unroll
            for (int j = 0; j < 4; j++) sa[i][j] = 0.f;
#pragma unroll 4
        for (int n = 0; n < DS; n++) {
            float a[4], bb[4];
#pragma unroll
            for (int i = 0; i < 4; i++) a[i]  = S.Cn[n][ly * 4 + i];
#pragma unroll
            for (int j = 0; j < 4; j++) bb[j] = S.Bn[n][px * 4 + j];
#pragma unroll
            for (int i = 0; i < 4; i++)
#pragma unroll
                for (int j = 0; j < 4; j++)
                    sa[i][j] = fmaf(a[i], bb[j], sa[i][j]);
        }
#pragma unroll
        for (int i = 0; i < 4; i++) {
            int l  = ly * 4 + i;
            int lg = lt * 128 + l;
            float al = S.acsl[l];
#pragma unroll
            for (int j = 0; j < 4; j++) {
                int sl = px * 4 + j;
                int sg = s0 + sl;
                float w = (sg <= lg) ? expf(al - S.acss[sl]) * sa[i][j] : 0.f;
                S.Pt[sl][l] = w;
            }
        }
        __syncthreads();
#pragma unroll 8
        for (int s = 0; s < 32; s++) {
            float a[4], bb[8];
#pragma unroll
            for (int i = 0; i < 4; i++) a[i] = S.Pt[s][ly * 4 + i];
#pragma unroll
            for (int j = 0; j < 4; j++) {
                bb[j]     = S.Xd[s][px * 4 + j];
                bb[4 + j] = S.Xd[s][32 + px * 4 + j];
            }
#pragma unroll
            for (int i = 0; i < 4; i++)
#pragma unroll
                for (int j = 0; j < 8; j++)
                    yacc[i][j] = fmaf(a[i], bb[j], yacc[i][j]);
        }
    }

    float oacc[4][8];
#pragma unroll
    for (int i = 0; i < 4; i++)
#pragma unroll
        for (int j = 0; j < 8; j++) oacc[i][j] = 0.f;
#pragma unroll 4
    for (int n = 0; n < DS; n++) {
        float a[4], bb[8];
#pragma unroll
        for (int i = 0; i < 4; i++) a[i] = S.Cn[n][ly * 4 + i];
#pragma unroll
        for (int j = 0; j < 4; j++) {
            bb[j]     = S.Pvn[n][px * 4 + j];
            bb[4 + j] = S.Pvn[n][32 + px * 4 + j];
        }
#pragma unroll
        for (int i = 0; i < 4; i++)
#pragma unroll
            for (int j = 0; j < 8; j++)
                oacc[i][j] = fmaf(a[i], bb[j], oacc[i][j]);
    }

    const float Dh = Dvec[h];
#pragma unroll
    for (int i = 0; i < 4; i++) {
        int l = ly * 4 + i;
        size_t row = rowBase + lt * 128 + l;
        float el = expf(S.acsl[l]);
#pragma unroll
        for (int j = 0; j < 8; j++) {
            int p = (j < 4) ? (px * 4 + j) : (32 + px * 4 + j - 4);
            float xs = g_conv[row * CONV_DIM + h * HD + p];
            g_y[row * DI + h * HD + p] = yacc[i][j] + el * oacc[i][j] + Dh * xs;
        }
    }
}

// ---------------- gate with silu(z) + RMSNorm ----------------
__global__ void __launch_bounds__(256) gate_norm_kernel(const float* __restrict__ norm_w)
{
    const int row = blockIdx.x;
    const float* yrow = &g_y[(size_t)row * DI];
    const float* zrow = &g_zxbcdt[(size_t)row * DPROJ];
    float vals[16];
    float ss = 0.f;
#pragma unroll
    for (int it = 0; it < 16; it++) {
        int i = threadIdx.x + it * 256;
        float z  = zrow[i];
        float yg = yrow[i] * (z / (1.f + expf(-z)));
        vals[it] = yg;
        ss = fmaf(yg, yg, ss);
    }
    __shared__ float red[8];
#pragma unroll
    for (int o = 16; o > 0; o >>= 1) ss += __shfl_xor_sync(0xffffffffu, ss, o);
    if ((threadIdx.x & 31) == 0) red[threadIdx.x >> 5] = ss;
    __syncthreads();
    float tot = 0.f;
#pragma unroll
    for (int w = 0; w < 8; w++) tot += red[w];
    float scale = rsqrtf(tot / (float)DI + EPSV);
    float* yw = &g_y[(size_t)row * DI];
#pragma unroll
    for (int it = 0; it < 16; it++) {
        int i = threadIdx.x + it * 256;
        yw[i] = vals[it] * scale * norm_w[i];
    }
}

// ---------------- launch ----------------
extern "C" void kernel_launch(void* const* d_in, const int* in_sizes, int n_in,
                              void* d_out, int out_size)
{
    (void)in_sizes; (void)n_in; (void)out_size;
    const float* x        = (const float*)d_in[0];
    const float* in_proj  = (const float*)d_in[1];
    const float* conv_w   = (const float*)d_in[2];
    const float* conv_b   = (const float*)d_in[3];
    const float* dt_bias  = (const float*)d_in[4];
    const float* A_log    = (const float*)d_in[5];
    const float* Dv       = (const float*)d_in[6];
    const float* norm_w   = (const float*)d_in[7];
    const float* out_proj = (const float*)d_in[8];
    float* out = (float*)d_out;

    float* zx = nullptr;
    float* yb = nullptr;
    cudaGetSymbolAddress((void**)&zx, g_zxbcdt);
    cudaGetSymbolAddress((void**)&yb, g_y);

    cudaFuncSetAttribute(y_kernel, cudaFuncAttributeMaxDynamicSharedMemorySize,
                         (int)sizeof(YS));

    // 1. in_proj GEMM (bf16x3, m16n8k16, double-buffered)
    gemm_bf16x3_tn<<<dim3((DPROJ + 127) / 128, BL / 128), 256>>>(x, in_proj, zx, BL, DPROJ, DM);
    // 2. depthwise conv + silu
    conv_silu_kernel<<<(BL * CONV_DIM + 255) / 256, 256>>>(conv_w, conv_b);
    // 3. dt = softplus
    dt_kernel<<<(BL * NH + 255) / 256, 256>>>(dt_bias);
    // 4. per-chunk cumsum of dA
    scan_kernel<<<B_SZ * NH * NC, CH>>>(A_log);
    // 5. per-chunk states
    states_kernel<<<B_SZ * NC * NH, 256>>>();
    // 6. inter-chunk recurrence
    chunk_rec_kernel<<<(B_SZ * NH * HD * DS + 255) / 256, 256>>>();
    // 7. SSD core -> Y
    y_kernel<<<dim3(B_SZ * NC * NH, 2), 256, sizeof(YS)>>>(Dv);
    // 8. gate + RMSNorm
    gate_norm_kernel<<<BL, 256>>>(norm_w);
    // 9. out_proj GEMM (bf16x3, m16n8k16, double-buffered)
    gemm_bf16x3_tn<<<dim3(DM / 128, BL / 128), 256>>>(yb, out_proj, out, BL, DM, DI);
}

// round 10
// speedup vs baseline: 1.6551x; 1.0976x over previous
#include <cuda_runtime.h>
#include <cuda_bf16.h>
#include <math.h>
#include <stdint.h>

// ---------------- problem constants ----------------
#define B_SZ   2
#define SEQL   2048
#define DM     2048
#define DI     4096
#define DS     128
#define HD     64
#define NH     64
#define CH     256
#define NC     8
#define CONV_DIM 4352           // DI + 2*DS
#define DPROJ    8512           // 2*DI + 2*DS + NH
#define EPSV   1e-5f
#define BL     (B_SZ * SEQL)    // 4096 rows

// ---------------- device scratch (static, no cudaMalloc) ----------------
__device__ float g_zxbcdt[(size_t)BL * DPROJ];     // in_proj output
__device__ float g_conv  [(size_t)BL * CONV_DIM];  // conv+silu output
__device__ float g_dt    [BL * NH];                // softplus(dt)
__device__ float g_acs   [B_SZ * NH * NC * CH];    // per-chunk cumsum(dA)
__device__ float g_states[B_SZ * NC * NH * HD * DS];
__device__ float g_prev  [B_SZ * NC * NH * HD * DS];
__device__ float g_G     [(size_t)B_SZ * NC * CH * CH];  // C·B^T per (b,c)  (4MB)
__device__ float g_y     [(size_t)BL * DI];        // Y then normalized y

extern __shared__ char dyn_smem[];   // used by y_kernel only

// ===== bf16x3 tensor-core GEMM (hi/lo split, m16n8k16, double-buffered) =====
__device__ __forceinline__ void mma_bf16(float c[4], const uint32_t a[4],
                                         const uint32_t b[2])
{
    asm volatile(
        "mma.sync.aligned.m16n8k16.row.col.f32.bf16.bf16.f32 "
        "{%0,%1,%2,%3}, {%4,%5,%6,%7}, {%8,%9}, {%0,%1,%2,%3};\n"
        : "+f"(c[0]), "+f"(c[1]), "+f"(c[2]), "+f"(c[3])
        : "r"(a[0]), "r"(a[1]), "r"(a[2]), "r"(a[3]),
          "r"(b[0]), "r"(b[1]));
}

__device__ __forceinline__ uint2 split_pack2(float x, float y)
{
    __nv_bfloat162 h = __floats2bfloat162_rn(x, y);
    float rx = x - __low2float(h);
    float ry = y - __high2float(h);
    __nv_bfloat162 l = __floats2bfloat162_rn(rx, ry);
    uint2 r;
    r.x = *reinterpret_cast<uint32_t*>(&h);
    r.y = *reinterpret_cast<uint32_t*>(&l);
    return r;
}

#define KSB   16
#define QSTR  12

__global__ void __launch_bounds__(256, 2) gemm_bf16x3_tn(const float* __restrict__ A,
                                                         const float* __restrict__ Bw,
                                                         float* __restrict__ C,
                                                         int M, int N, int K)
{
    __shared__ uint2 As2[2][128][QSTR];
    __shared__ uint2 Bs2[2][128][QSTR];

    const int tid  = threadIdx.x;
    const int warp = tid >> 5;
    const int lane = tid & 31;
    const int g    = lane >> 2;
    const int tig  = lane & 3;
    const int wm   = warp >> 2;
    const int wn   = warp & 3;

    const int mBase = blockIdx.y * 128;
    const int nBase = blockIdx.x * 128;

    const int rL = tid >> 1;
    const int hb = (tid & 1) * 8;
    const int pb = hb >> 1;

    float acc[4][4][4];
#pragma unroll
    for (int mt = 0; mt < 4; mt++)
#pragma unroll
        for (int nt = 0; nt < 4; nt++)
#pragma unroll
            for (int e = 0; e < 4; e++) acc[mt][nt][e] = 0.f;

    const float* aP = A  + (size_t)(mBase + rL) * K + hb;
    const int    gn = nBase + rL;
    const float* bP = Bw + (size_t)gn * K + hb;
    const bool   ok = (gn < N);
    const float4 z4 = make_float4(0.f, 0.f, 0.f, 0.f);

    auto store8 = [&](uint2 (*dst)[QSTR], float4 v0, float4 v1) {
        dst[rL][pb + 0] = split_pack2(v0.x, v0.y);
        dst[rL][pb + 1] = split_pack2(v0.z, v0.w);
        dst[rL][pb + 2] = split_pack2(v1.x, v1.y);
        dst[rL][pb + 3] = split_pack2(v1.z, v1.w);
    };

    {
        float4 a0 = *reinterpret_cast<const float4*>(aP);
        float4 a1 = *reinterpret_cast<const float4*>(aP + 4);
        float4 b0 = ok ? *reinterpret_cast<const float4*>(bP)     : z4;
        float4 b1 = ok ? *reinterpret_cast<const float4*>(bP + 4) : z4;
        store8(As2[0], a0, a1);
        store8(Bs2[0], b0, b1);
    }
    __syncthreads();

    const int nk = K / KSB;
    for (int kt = 0; kt < nk; kt++) {
        const int cur  = kt & 1;
        const bool more = (kt + 1 < nk);
        float4 na0, na1, nb0, nb1;
        if (more) {
            const int kc = (kt + 1) * KSB;
            na0 = *reinterpret_cast<const float4*>(aP + kc);
            na1 = *reinterpret_cast<const float4*>(aP + kc + 4);
            nb0 = ok ? *reinterpret_cast<const float4*>(bP + kc)     : z4;
            nb1 = ok ? *reinterpret_cast<const float4*>(bP + kc + 4) : z4;
        }

        uint32_t bh[4][2], bl[4][2];
#pragma unroll
        for (int nt = 0; nt < 4; nt++) {
            const int n = wn * 32 + nt * 8 + g;
            uint2 q0 = Bs2[cur][n][tig];
            uint2 q1 = Bs2[cur][n][tig + 4];
            bh[nt][0] = q0.x; bl[nt][0] = q0.y;
            bh[nt][1] = q1.x; bl[nt][1] = q1.y;
        }
#pragma unroll
        for (int mt = 0; mt < 4; mt++) {
            const int m0 = wm * 64 + mt * 16 + g;
            uint2 p00 = As2[cur][m0][tig];
            uint2 p10 = As2[cur][m0 + 8][tig];
            uint2 p01 = As2[cur][m0][tig + 4];
            uint2 p11 = As2[cur][m0 + 8][tig + 4];
            uint32_t ah[4] = { p00.x, p10.x, p01.x, p11.x };
            uint32_t al[4] = { p00.y, p10.y, p01.y, p11.y };
#pragma unroll
            for (int nt = 0; nt < 4; nt++) {
                mma_bf16(acc[mt][nt], ah, bh[nt]);
                mma_bf16(acc[mt][nt], ah, bl[nt]);
                mma_bf16(acc[mt][nt], al, bh[nt]);
            }
        }

        if (more) {
            const int nxt = cur ^ 1;
            store8(As2[nxt], na0, na1);
            store8(Bs2[nxt], nb0, nb1);
        }
        __syncthreads();
    }

#pragma unroll
    for (int mt = 0; mt < 4; mt++) {
        const int row0 = mBase + wm * 64 + mt * 16 + g;
#pragma unroll
        for (int nt = 0; nt < 4; nt++) {
            const int col = nBase + wn * 32 + nt * 8 + 2 * tig;
            if (col < N) {
                float2 v01 = make_float2(acc[mt][nt][0], acc[mt][nt][1]);
                float2 v23 = make_float2(acc[mt][nt][2], acc[mt][nt][3]);
                *reinterpret_cast<float2*>(&C[(size_t)row0 * N + col])       = v01;
                *reinterpret_cast<float2*>(&C[(size_t)(row0 + 8) * N + col]) = v23;
            }
        }
    }
}

// ---------------- depthwise causal conv (width 4) + bias + silu ----------------
__global__ void conv_silu_kernel(const float* __restrict__ conv_w,
                                 const float* __restrict__ conv_b)
{
    int idx = blockIdx.x * blockDim.x + threadIdx.x;
    if (idx >= BL * CONV_DIM) return;
    int ch = idx % CONV_DIM;
    int l  = (idx / CONV_DIM) % SEQL;
    int b  = idx / (CONV_DIM * SEQL);
    float acc = conv_b[ch];
#pragma unroll
    for (int j = 0; j < 4; j++) {
        int t = l - 3 + j;
        if (t >= 0)
            acc = fmaf(conv_w[ch * 4 + j],
                       g_zxbcdt[(size_t)(b * SEQL + t) * DPROJ + DI + ch], acc);
    }
    g_conv[(size_t)(b * SEQL + l) * CONV_DIM + ch] = acc / (1.f + expf(-acc));
}

// ---------------- dt = softplus(raw + dt_bias) ----------------
__global__ void dt_kernel(const float* __restrict__ dt_bias)
{
    int idx = blockIdx.x * blockDim.x + threadIdx.x;
    if (idx >= BL * NH) return;
    int hh  = idx % NH;
    int row = idx / NH;
    float v = g_zxbcdt[(size_t)row * DPROJ + DI + CONV_DIM + hh] + dt_bias[hh];
    g_dt[idx] = (v > 20.f) ? v : log1pf(expf(v));
}

// ---------------- per-chunk inclusive cumsum of dA = dt * A ----------------
__global__ void scan_kernel(const float* __restrict__ A_log)
{
    const int bc = blockIdx.x;
    const int c  = bc % NC;
    const int h  = (bc / NC) % NH;
    const int b  = bc / (NC * NH);
    const int l  = threadIdx.x;
    const float A = -expf(A_log[h]);
    float v = g_dt[(size_t)(b * SEQL + c * CH + l) * NH + h] * A;
    __shared__ float s[CH];
    s[l] = v;
    __syncthreads();
    for (int off = 1; off < CH; off <<= 1) {
        float t = (l >= off) ? s[l - off] : 0.f;
        __syncthreads();
        s[l] += t;
        __syncthreads();
    }
    g_acs[(size_t)bc * CH + l] = s[l];
}

// ---------------- G[b,c,l,s] = sum_n C[l,n] B[s,n]  (h-independent, hoisted) ----
// grid (B_SZ*NC, 3): tile t -> (lt,st) in {(0,0),(1,0),(1,1)}  (lower triangle)
__global__ void __launch_bounds__(256) gmat_kernel()
{
    __shared__ float Ct[32][129];
    __shared__ float Bt[32][129];
    const int tid = threadIdx.x;
    const int tx  = tid & 15;
    const int ty  = tid >> 4;
    const int bc  = blockIdx.x;
    const int c   = bc % NC;
    const int b   = bc / NC;
    const int t   = blockIdx.y;
    const int lt  = (t == 0) ? 0 : 1;
    const int st  = (t == 2) ? 1 : 0;
    const size_t rowBase = (size_t)(b * SEQL + c * CH);

    float acc[8][8];
#pragma unroll
    for (int i = 0; i < 8; i++)
#pragma unroll
        for (int j = 0; j < 8; j++) acc[i][j] = 0.f;

    for (int nb = 0; nb < DS; nb += 32) {
        __syncthreads();
#pragma unroll
        for (int it = 0; it < 4; it++) {
            int slot = tid + it * 256;
            int r  = slot >> 3;          // 0..127
            int n4 = (slot & 7) * 4;     // 0..28
            float4 cv = *reinterpret_cast<const float4*>(
                &g_conv[(rowBase + lt * 128 + r) * CONV_DIM + DI + DS + nb + n4]);
            Ct[n4 + 0][r] = cv.x; Ct[n4 + 1][r] = cv.y;
            Ct[n4 + 2][r] = cv.z; Ct[n4 + 3][r] = cv.w;
            float4 bv = *reinterpret_cast<const float4*>(
                &g_conv[(rowBase + st * 128 + r) * CONV_DIM + DI + nb + n4]);
            Bt[n4 + 0][r] = bv.x; Bt[n4 + 1][r] = bv.y;
            Bt[n4 + 2][r] = bv.z; Bt[n4 + 3][r] = bv.w;
        }
        __syncthreads();
#pragma unroll 8
        for (int n = 0; n < 32; n++) {
            float a[8], bb[8];
#pragma unroll
            for (int i = 0; i < 4; i++) {
                a[i]      = Ct[n][ty * 4 + i];
                a[4 + i]  = Ct[n][64 + ty * 4 + i];
                bb[i]     = Bt[n][tx * 4 + i];
                bb[4 + i] = Bt[n][64 + tx * 4 + i];
            }
#pragma unroll
            for (int i = 0; i < 8; i++)
#pragma unroll
                for (int j = 0; j < 8; j++)
                    acc[i][j] = fmaf(a[i], bb[j], acc[i][j]);
        }
    }

    float* Gb = g_G + (size_t)bc * CH * CH;
#pragma unroll
    for (int i = 0; i < 8; i++) {
        int l = lt * 128 + ((i < 4) ? (ty * 4 + i) : (64 + ty * 4 + i - 4));
#pragma unroll
        for (int j = 0; j < 8; j++) {
            int s = st * 128 + ((j < 4) ? (tx * 4 + j) : (64 + tx * 4 + j - 4));
            Gb[(size_t)l * CH + s] = acc[i][j];
        }
    }
}

// ---------------- per-chunk states ----------------
__global__ void __launch_bounds__(256) states_kernel()
{
    __shared__ float Bs[32][129];
    __shared__ float Xs[32][65];
    const int tid = threadIdx.x;
    const int tx  = tid & 15;
    const int ty  = tid >> 4;
    const int h = blockIdx.x % NH;
    const int c = (blockIdx.x / NH) % NC;
    const int b = blockIdx.x / (NH * NC);
    const size_t rowBase = (size_t)(b * SEQL + c * CH);
    const size_t acsBase = ((size_t)(b * NH + h) * NC + c) * CH;
    const float acsLast = g_acs[acsBase + CH - 1];

    float acc[4][8];
#pragma unroll
    for (int i = 0; i < 4; i++)
#pragma unroll
        for (int j = 0; j < 8; j++) acc[i][j] = 0.f;

    for (int s0 = 0; s0 < CH; s0 += 32) {
        __syncthreads();
#pragma unroll
        for (int it = 0; it < 4; it++) {
            int slot = tid + it * 256;
            int sr = slot >> 5;
            int n4 = (slot & 31) * 4;
            float4 v = *reinterpret_cast<const float4*>(
                &g_conv[(rowBase + s0 + sr) * CONV_DIM + DI + n4]);
            Bs[sr][n4 + 0] = v.x; Bs[sr][n4 + 1] = v.y;
            Bs[sr][n4 + 2] = v.z; Bs[sr][n4 + 3] = v.w;
        }
#pragma unroll
        for (int it = 0; it < 2; it++) {
            int slot = tid + it * 256;
            int sr = slot >> 4;
            int p4 = (slot & 15) * 4;
            size_t row = rowBase + s0 + sr;
            float sc = g_dt[row * NH + h] * expf(acsLast - g_acs[acsBase + s0 + sr]);
            float4 v = *reinterpret_cast<const float4*>(&g_conv[row * CONV_DIM + h * HD + p4]);
            Xs[sr][p4 + 0] = v.x * sc; Xs[sr][p4 + 1] = v.y * sc;
            Xs[sr][p4 + 2] = v.z * sc; Xs[sr][p4 + 3] = v.w * sc;
        }
        __syncthreads();
#pragma unroll 8
        for (int s = 0; s < 32; s++) {
            float a[4], bb[8];
#pragma unroll
            for (int i = 0; i < 4; i++) a[i] = Xs[s][ty * 4 + i];
#pragma unroll
            for (int j = 0; j < 4; j++) {
                bb[j]     = Bs[s][tx * 4 + j];
                bb[4 + j] = Bs[s][64 + tx * 4 + j];
            }
#pragma unroll
            for (int i = 0; i < 4; i++)
#pragma unroll
                for (int j = 0; j < 8; j++)
                    acc[i][j] = fmaf(a[i], bb[j], acc[i][j]);
        }
    }
    const size_t base = ((size_t)(b * NC + c) * NH + h) * (HD * DS);
#pragma unroll
    for (int i = 0; i < 4; i++) {
        int p = ty * 4 + i;
#pragma unroll
        for (int j = 0; j < 8; j++) {
            int n = (j < 4) ? (tx * 4 + j) : (64 + tx * 4 + j - 4);
            g_states[base + (size_t)p * DS + n] = acc[i][j];
        }
    }
}

// ---------------- inter-chunk recurrence ----------------
__global__ void chunk_rec_kernel()
{
    int idx = blockIdx.x * blockDim.x + threadIdx.x;
    if (idx >= B_SZ * NH * HD * DS) return;
    int n = idx % DS;
    int p = (idx / DS) % HD;
    int h = (idx / (DS * HD)) % NH;
    int b = idx / (DS * HD * NH);
    float prev = 0.f;
#pragma unroll
    for (int c = 0; c < NC; c++) {
        size_t off = (((size_t)(b * NC + c) * NH + h) * HD + p) * DS + n;
        g_prev[off] = prev;
        float cs = g_acs[((size_t)(b * NH + h) * NC + c) * CH + CH - 1];
        prev = expf(cs) * prev + g_states[off];
    }
}

// ---------------- SSD core (Phase A hoisted to gmat_kernel) ----------------
struct YS {
    float Cn [DS][129];   // C transposed (for Y_off)
    float Pt [32][129];   // masked decayed scores [s][l]
    float Xd [32][65];    // X*dt
    float Pvn[DS][65];    // prev transposed
    float acsl[128];
    float acss[32];
};

__global__ void __launch_bounds__(256) y_kernel(const float* __restrict__ Dvec)
{
    YS& S = *reinterpret_cast<YS*>(dyn_smem);
    const int tid = threadIdx.x;
    const int h  = blockIdx.x % NH;
    const int c  = (blockIdx.x / NH) % NC;
    const int b  = blockIdx.x / (NH * NC);
    const int lt = blockIdx.y;
    const size_t rowBase = (size_t)(b * SEQL + c * CH);
    const size_t acsBase = ((size_t)(b * NH + h) * NC + c) * CH;
    const int ly = tid >> 3;
    const int px = tid & 7;

    // G-tile load mapping: each thread owns one l-row, 16 s-columns
    const int gl = tid >> 1;              // 0..127
    const int sb = (tid & 1) * 16;        // 0 or 16
    const float* Gb = g_G + ((size_t)(b * NC + c) * CH + lt * 128 + gl) * CH;

#pragma unroll
    for (int it = 0; it < 16; it++) {
        int slot = tid + it * 256;
        int l  = slot >> 5;
        int n4 = (slot & 31) * 4;
        float4 v = *reinterpret_cast<const float4*>(
            &g_conv[(rowBase + lt * 128 + l) * CONV_DIM + DI + DS + n4]);
        S.Cn[n4 + 0][l] = v.x; S.Cn[n4 + 1][l] = v.y;
        S.Cn[n4 + 2][l] = v.z; S.Cn[n4 + 3][l] = v.w;
    }
    if (tid < 128) S.acsl[tid] = g_acs[acsBase + lt * 128 + tid];
    const size_t pvBase = ((size_t)(b * NC + c) * NH + h) * (HD * DS);
#pragma unroll
    for (int it = 0; it < 8; it++) {
        int slot = tid + it * 256;
        int p  = slot >> 5;
        int n4 = (slot & 31) * 4;
        float4 v = *reinterpret_cast<const float4*>(&g_prev[pvBase + (size_t)p * DS + n4]);
        S.Pvn[n4 + 0][p] = v.x; S.Pvn[n4 + 1][p] = v.y;
        S.Pvn[n4 + 2][p] = v.z; S.Pvn[n4 + 3][p] = v.w;
    }

    float yacc[4][8];
#pragma unroll
    for (int i = 0; i < 4; i++)
#pragma unroll
        for (int j = 0; j < 8; j++) yacc[i][j] = 0.f;

    const int nst = 4 * (lt + 1);
    for (int st = 0; st < nst; st++) {
        const int s0 = st * 32;
        // prefetch G tile into regs (no smem dependency)
        float4 gq[4];
#pragma unroll
        for (int q = 0; q < 4; q++)
            gq[q] = *reinterpret_cast<const float4*>(Gb + s0 + sb + 4 * q);

        __syncthreads();   // previous phase-B reads of Xd/Pt complete
#pragma unroll
        for (int it = 0; it < 2; it++) {
            int slot = tid + it * 256;
            int sr = slot >> 4;
            int p4 = (slot & 15) * 4;
            size_t row = rowBase + s0 + sr;
            float dt = g_dt[row * NH + h];
            float4 v = *reinterpret_cast<const float4*>(&g_conv[row * CONV_DIM + h * HD + p4]);
            S.Xd[sr][p4 + 0] = v.x * dt; S.Xd[sr][p4 + 1] = v.y * dt;
            S.Xd[sr][p4 + 2] = v.z * dt; S.Xd[sr][p4 + 3] = v.w * dt;
        }
        if (tid < 32) S.acss[tid] = g_acs[acsBase + s0 + tid];
        __syncthreads();   // acss/Xd visible

        // mask + decay on G tile -> Pt[s][l]
        {
            const int lg = lt * 128 + gl;
            const float al = S.acsl[gl];
            const float* gf = reinterpret_cast<const float*>(gq);
#pragma unroll
            for (int q = 0; q < 16; q++) {
                int sl = sb + q;
                int sg = s0 + sl;
                float w = (sg <= lg) ? expf(al - S.acss[sl]) * gf[q] : 0.f;
                S.Pt[sl][gl] = w;
            }
        }
        __syncthreads();   // Pt ready

        // Phase B: Y[l,p] += sum_s P[l,s] Xd[s,p]
#pragma unroll 8
        for (int s = 0; s < 32; s++) {
            float a[4], bb[8];
#pragma unroll
            for (int i = 0; i < 4; i++) a[i] = S.Pt[s][ly * 4 + i];
#pragma unroll
            for (int j = 0; j < 4; j++) {
                bb[j]     = S.Xd[s][px * 4 + j];
                bb[4 + j] = S.Xd[s][32 + px * 4 + j];
            }
#pragma unroll
            for (int i = 0; i < 4; i++)
#pragma unroll
                for (int j = 0; j < 8; j++)
                    yacc[i][j] = fmaf(a[i], bb[j], yacc[i][j]);
        }
    }

    // Y_off: O[l,p] = sum_n C[l,n] prev[p,n]
    float oacc[4][8];
#pragma unroll
    for (int i = 0; i < 4; i++)
#pragma unroll
        for (int j = 0; j < 8; j++) oacc[i][j] = 0.f;
#pragma unroll 4
    for (int n = 0; n < DS; n++) {
        float a[4], bb[8];
#pragma unroll
        for (int i = 0; i < 4; i++) a[i] = S.Cn[n][ly * 4 + i];
#pragma unroll
        for (int j = 0; j < 4; j++) {
            bb[j]     = S.Pvn[n][px * 4 + j];
            bb[4 + j] = S.Pvn[n][32 + px * 4 + j];
        }
#pragma unroll
        for (int i = 0; i < 4; i++)
#pragma unroll
            for (int j = 0; j < 8; j++)
                oacc[i][j] = fmaf(a[i], bb[j], oacc[i][j]);
    }

    const float Dh = Dvec[h];
#pragma unroll
    for (int i = 0; i < 4; i++) {
        int l = ly * 4 + i;
        size_t row = rowBase + lt * 128 + l;
        float el = expf(S.acsl[l]);
#pragma unroll
        for (int j = 0; j < 8; j++) {
            int p = (j < 4) ? (px * 4 + j) : (32 + px * 4 + j - 4);
            float xs = g_conv[row * CONV_DIM + h * HD + p];
            g_y[row * DI + h * HD + p] = yacc[i][j] + el * oacc[i][j] + Dh * xs;
        }
    }
}

// ---------------- gate with silu(z) + RMSNorm ----------------
__global__ void __launch_bounds__(256) gate_norm_kernel(const float* __restrict__ norm_w)
{
    const int row = blockIdx.x;
    const float* yrow = &g_y[(size_t)row * DI];
    const float* zrow = &g_zxbcdt[(size_t)row * DPROJ];
    float vals[16];
    float ss = 0.f;
#pragma unroll
    for (int it = 0; it < 16; it++) {
        int i = threadIdx.x + it * 256;
        float z  = zrow[i];
        float yg = yrow[i] * (z / (1.f + expf(-z)));
        vals[it] = yg;
        ss = fmaf(yg, yg, ss);
    }
    __shared__ float red[8];
#pragma unroll
    for (int o = 16; o > 0; o >>= 1) ss += __shfl_xor_sync(0xffffffffu, ss, o);
    if ((threadIdx.x & 31) == 0) red[threadIdx.x >> 5] = ss;
    __syncthreads();
    float tot = 0.f;
#pragma unroll
    for (int w = 0; w < 8; w++) tot += red[w];
    float scale = rsqrtf(tot / (float)DI + EPSV);
    float* yw = &g_y[(size_t)row * DI];
#pragma unroll
    for (int it = 0; it < 16; it++) {
        int i = threadIdx.x + it * 256;
        yw[i] = vals[it] * scale * norm_w[i];
    }
}

// ---------------- launch ----------------
extern "C" void kernel_launch(void* const* d_in, const int* in_sizes, int n_in,
                              void* d_out, int out_size)
{
    (void)in_sizes; (void)n_in; (void)out_size;
    const float* x        = (const float*)d_in[0];
    const float* in_proj  = (const float*)d_in[1];
    const float* conv_w   = (const float*)d_in[2];
    const float* conv_b   = (const float*)d_in[3];
    const float* dt_bias  = (const float*)d_in[4];
    const float* A_log    = (const float*)d_in[5];
    const float* Dv       = (const float*)d_in[6];
    const float* norm_w   = (const float*)d_in[7];
    const float* out_proj = (const float*)d_in[8];
    float* out = (float*)d_out;

    float* zx = nullptr;
    float* yb = nullptr;
    cudaGetSymbolAddress((void**)&zx, g_zxbcdt);
    cudaGetSymbolAddress((void**)&yb, g_y);

    cudaFuncSetAttribute(y_kernel, cudaFuncAttributeMaxDynamicSharedMemorySize,
                         (int)sizeof(YS));

    // 1. in_proj GEMM (bf16x3, m16n8k16, double-buffered)
    gemm_bf16x3_tn<<<dim3((DPROJ + 127) / 128, BL / 128), 256>>>(x, in_proj, zx, BL, DPROJ, DM);
    // 2. depthwise conv + silu
    conv_silu_kernel<<<(BL * CONV_DIM + 255) / 256, 256>>>(conv_w, conv_b);
    // 3. dt = softplus
    dt_kernel<<<(BL * NH + 255) / 256, 256>>>(dt_bias);
    // 4. per-chunk cumsum of dA
    scan_kernel<<<B_SZ * NH * NC, CH>>>(A_log);
    // 5. G = C·B^T per (b,c)  (hoisted, h-independent)
    gmat_kernel<<<dim3(B_SZ * NC, 3), 256>>>();
    // 6. per-chunk states
    states_kernel<<<B_SZ * NC * NH, 256>>>();
    // 7. inter-chunk recurrence
    chunk_rec_kernel<<<(B_SZ * NH * HD * DS + 255) / 256, 256>>>();
    // 8. SSD core -> Y
    y_kernel<<<dim3(B_SZ * NC * NH, 2), 256, sizeof(YS)>>>(Dv);
    // 9. gate + RMSNorm
    gate_norm_kernel<<<BL, 256>>>(norm_w);
    // 10. out_proj GEMM (bf16x3, m16n8k16, double-buffered)
    gemm_bf16x3_tn<<<dim3(DM / 128, BL / 128), 256>>>(yb, out_proj, out, BL, DM, DI);
}

// round 14
// speedup vs baseline: 1.6942x; 1.0236x over previous
#include <cuda_runtime.h>
#include <cuda_bf16.h>
#include <math.h>
#include <stdint.h>

// ---------------- problem constants ----------------
#define B_SZ   2
#define SEQL   2048
#define DM     2048
#define DI     4096
#define DS     128
#define HD     64
#define NH     64
#define CH     256
#define NC     8
#define CONV_DIM 4352           // DI + 2*DS
#define DPROJ    8512           // 2*DI + 2*DS + NH
#define EPSV   1e-5f
#define BL     (B_SZ * SEQL)    // 4096 rows

// ---------------- device scratch (static, no cudaMalloc) ----------------
__device__ float g_zxbcdt[(size_t)BL * DPROJ];     // in_proj output
__device__ float g_conv  [(size_t)BL * CONV_DIM];  // conv+silu output
__device__ float g_dt    [BL * NH];                // softplus(dt)
__device__ float g_acs   [B_SZ * NH * NC * CH];    // per-chunk cumsum(dA)
__device__ float g_states[B_SZ * NC * NH * HD * DS];
__device__ float g_prev  [B_SZ * NC * NH * HD * DS];
__device__ float g_G     [(size_t)B_SZ * NC * CH * CH];  // C·B^T per (b,c)
__device__ float g_y     [(size_t)BL * DI];        // Y then normalized y

extern __shared__ char dyn_smem[];   // gemm + y_kernel dynamic smem

// ===== bf16x3 tensor-core GEMM (hi/lo split, m16n8k16) =====
// C[M,N] = A[M,K] * Bw[N,K]^T.  fp32 in/out, ~fp32 accuracy via
// x = hi + lo (both bf16), C += hi*hi + hi*lo + lo*hi (fp32 accum).
// 128x128 tile, K-step 16, FOUR smem stages, ONE __syncthreads per 2 steps.
// Layout identical to the proven 2-stage version (stride 12 uint2 rows).
// 256 threads (8 warps, 2x4 -> 64x32 warp tile), 2 CTAs/SM, 96KB dyn smem.

__device__ __forceinline__ void mma_bf16(float c[4], const uint32_t a[4],
                                         const uint32_t b[2])
{
    asm volatile(
        "mma.sync.aligned.m16n8k16.row.col.f32.bf16.bf16.f32 "
        "{%0,%1,%2,%3}, {%4,%5,%6,%7}, {%8,%9}, {%0,%1,%2,%3};\n"
        : "+f"(c[0]), "+f"(c[1]), "+f"(c[2]), "+f"(c[3])
        : "r"(a[0]), "r"(a[1]), "r"(a[2]), "r"(a[3]),
          "r"(b[0]), "r"(b[1]));
}

__device__ __forceinline__ uint2 split_pack2(float x, float y)
{
    __nv_bfloat162 h = __floats2bfloat162_rn(x, y);
    float rx = x - __low2float(h);
    float ry = y - __high2float(h);
    __nv_bfloat162 l = __floats2bfloat162_rn(rx, ry);
    uint2 r;
    r.x = *reinterpret_cast<uint32_t*>(&h);
    r.y = *reinterpret_cast<uint32_t*>(&l);
    return r;
}

#define KSB   16   // K-step
#define QSTR  12   // uint2 row stride (proven conflict-free in 2-stage version)
#define STAGE_U2 (128 * QSTR)              // uint2 elements per stage
#define GEMM_SMEM (8 * STAGE_U2 * (int)sizeof(uint2))   // 4 stages x 2 mats = 98304 B

// store one thread's 8 floats (4 value-pairs) into a stage
__device__ __forceinline__ void store8(uint2* stage, int rL, int pb,
                                       float4 v0, float4 v1)
{
    uint2* row = stage + rL * QSTR;
    row[pb + 0] = split_pack2(v0.x, v0.y);
    row[pb + 1] = split_pack2(v0.z, v0.w);
    row[pb + 2] = split_pack2(v1.x, v1.y);
    row[pb + 3] = split_pack2(v1.z, v1.w);
}

// one K-step of 48 HMMA on a stage pair
__device__ __forceinline__ void compute16(const uint2* As, const uint2* Bs,
                                          int wm, int wn, int g, int tig,
                                          float acc[4][4][4])
{
    uint32_t bh[4][2], bl[4][2];
#pragma unroll
    for (int nt = 0; nt < 4; nt++) {
        const int n = wn * 32 + nt * 8 + g;
        uint2 q0 = Bs[n * QSTR + tig];
        uint2 q1 = Bs[n * QSTR + tig + 4];
        bh[nt][0] = q0.x; bl[nt][0] = q0.y;
        bh[nt][1] = q1.x; bl[nt][1] = q1.y;
    }
#pragma unroll
    for (int mt = 0; mt < 4; mt++) {
        const int m0 = wm * 64 + mt * 16 + g;
        uint2 p00 = As[m0 * QSTR + tig];
        uint2 p10 = As[(m0 + 8) * QSTR + tig];
        uint2 p01 = As[m0 * QSTR + tig + 4];
        uint2 p11 = As[(m0 + 8) * QSTR + tig + 4];
        uint32_t ah[4] = { p00.x, p10.x, p01.x, p11.x };
        uint32_t al[4] = { p00.y, p10.y, p01.y, p11.y };
#pragma unroll
        for (int nt = 0; nt < 4; nt++) {
            mma_bf16(acc[mt][nt], ah, bh[nt]);   // hi*hi
            mma_bf16(acc[mt][nt], ah, bl[nt]);   // hi*lo
            mma_bf16(acc[mt][nt], al, bh[nt]);   // lo*hi
        }
    }
}

__global__ void __launch_bounds__(256, 2) gemm_bf16x3_tn(const float* __restrict__ A,
                                                         const float* __restrict__ Bw,
                                                         float* __restrict__ C,
                                                         int M, int N, int K)
{
    uint2* AsBase = reinterpret_cast<uint2*>(dyn_smem);        // 4 stages
    uint2* BsBase = AsBase + 4 * STAGE_U2;                     // 4 stages

    const int tid  = threadIdx.x;
    const int warp = tid >> 5;
    const int lane = tid & 31;
    const int g    = lane >> 2;      // 0..7
    const int tig  = lane & 3;       // 0..3
    const int wm   = warp >> 2;      // 0..1
    const int wn   = warp & 3;       // 0..3

    const int mBase = blockIdx.y * 128;
    const int nBase = blockIdx.x * 128;

    const int rL = tid >> 1;         // 0..127
    const int hb = (tid & 1) * 8;    // k offset 0 or 8
    const int pb = hb >> 1;          // pair base 0 or 4

    float acc[4][4][4];
#pragma unroll
    for (int mt = 0; mt < 4; mt++)
#pragma unroll
        for (int nt = 0; nt < 4; nt++)
#pragma unroll
            for (int e = 0; e < 4; e++) acc[mt][nt][e] = 0.f;

    const float* aP = A  + (size_t)(mBase + rL) * K + hb;
    const int    gn = nBase + rL;
    const float* bP = Bw + (size_t)gn * K + hb;
    const bool   ok = (gn < N);
    const float4 z4 = make_float4(0.f, 0.f, 0.f, 0.f);

    // prologue: stages 0 and 1 (steps 0, 1)
#pragma unroll
    for (int s = 0; s < 2; s++) {
        const int kc = s * KSB;
        float4 a0 = *reinterpret_cast<const float4*>(aP + kc);
        float4 a1 = *reinterpret_cast<const float4*>(aP + kc + 4);
        float4 b0 = ok ? *reinterpret_cast<const float4*>(bP + kc)     : z4;
        float4 b1 = ok ? *reinterpret_cast<const float4*>(bP + kc + 4) : z4;
        store8(AsBase + s * STAGE_U2, rL, pb, a0, a1);
        store8(BsBase + s * STAGE_U2, rL, pb, b0, b1);
    }
    __syncthreads();

    const int nk = K / KSB;          // even for K = 2048 / 4096
    for (int j = 0; j < nk; j += 2) {
        float4 a0, a1, b0, b1;
        const bool m2 = (j + 2 < nk);
        const bool m3 = (j + 3 < nk);

        if (m2) {
            const int kc = (j + 2) * KSB;
            a0 = *reinterpret_cast<const float4*>(aP + kc);
            a1 = *reinterpret_cast<const float4*>(aP + kc + 4);
            b0 = ok ? *reinterpret_cast<const float4*>(bP + kc)     : z4;
            b1 = ok ? *reinterpret_cast<const float4*>(bP + kc + 4) : z4;
        }

        compute16(AsBase + (j & 3) * STAGE_U2, BsBase + (j & 3) * STAGE_U2,
                  wm, wn, g, tig, acc);

        if (m2) {
            const int s2 = (j + 2) & 3;
            store8(AsBase + s2 * STAGE_U2, rL, pb, a0, a1);
            store8(BsBase + s2 * STAGE_U2, rL, pb, b0, b1);
        }

        if (m3) {
            const int kc = (j + 3) * KSB;
            a0 = *reinterpret_cast<const float4*>(aP + kc);
            a1 = *reinterpret_cast<const float4*>(aP + kc + 4);
            b0 = ok ? *reinterpret_cast<const float4*>(bP + kc)     : z4;
            b1 = ok ? *reinterpret_cast<const float4*>(bP + kc + 4) : z4;
        }

        compute16(AsBase + ((j + 1) & 3) * STAGE_U2, BsBase + ((j + 1) & 3) * STAGE_U2,
                  wm, wn, g, tig, acc);

        if (m3) {
            const int s3 = (j + 3) & 3;
            store8(AsBase + s3 * STAGE_U2, rL, pb, a0, a1);
            store8(BsBase + s3 * STAGE_U2, rL, pb, b0, b1);
        }
        __syncthreads();
    }

    // epilogue
#pragma unroll
    for (int mt = 0; mt < 4; mt++) {
        const int row0 = mBase + wm * 64 + mt * 16 + g;
#pragma unroll
        for (int nt = 0; nt < 4; nt++) {
            const int col = nBase + wn * 32 + nt * 8 + 2 * tig;
            if (col < N) {
                float2 v01 = make_float2(acc[mt][nt][0], acc[mt][nt][1]);
                float2 v23 = make_float2(acc[mt][nt][2], acc[mt][nt][3]);
                *reinterpret_cast<float2*>(&C[(size_t)row0 * N + col])       = v01;
                *reinterpret_cast<float2*>(&C[(size_t)(row0 + 8) * N + col]) = v23;
            }
        }
    }
}

// ---------------- depthwise causal conv (width 4) + bias + silu ----------------
__global__ void conv_silu_kernel(const float* __restrict__ conv_w,
                                 const float* __restrict__ conv_b)
{
    int idx = blockIdx.x * blockDim.x + threadIdx.x;
    if (idx >= BL * CONV_DIM) return;
    int ch = idx % CONV_DIM;
    int l  = (idx / CONV_DIM) % SEQL;
    int b  = idx / (CONV_DIM * SEQL);
    float acc = conv_b[ch];
#pragma unroll
    for (int j = 0; j < 4; j++) {
        int t = l - 3 + j;
        if (t >= 0)
            acc = fmaf(conv_w[ch * 4 + j],
                       g_zxbcdt[(size_t)(b * SEQL + t) * DPROJ + DI + ch], acc);
    }
    g_conv[(size_t)(b * SEQL + l) * CONV_DIM + ch] = acc / (1.f + expf(-acc));
}

// ---------------- dt = softplus(raw + dt_bias) ----------------
__global__ void dt_kernel(const float* __restrict__ dt_bias)
{
    int idx = blockIdx.x * blockDim.x + threadIdx.x;
    if (idx >= BL * NH) return;
    int hh  = idx % NH;
    int row = idx / NH;
    float v = g_zxbcdt[(size_t)row * DPROJ + DI + CONV_DIM + hh] + dt_bias[hh];
    g_dt[idx] = (v > 20.f) ? v : log1pf(expf(v));
}

// ---------------- per-chunk inclusive cumsum of dA = dt * A ----------------
__global__ void scan_kernel(const float* __restrict__ A_log)
{
    const int bc = blockIdx.x;
    const int c  = bc % NC;
    const int h  = (bc / NC) % NH;
    const int b  = bc / (NC * NH);
    const int l  = threadIdx.x;
    const float A = -expf(A_log[h]);
    float v = g_dt[(size_t)(b * SEQL + c * CH + l) * NH + h] * A;
    __shared__ float s[CH];
    s[l] = v;
    __syncthreads();
    for (int off = 1; off < CH; off <<= 1) {
        float t = (l >= off) ? s[l - off] : 0.f;
        __syncthreads();
        s[l] += t;
        __syncthreads();
    }
    g_acs[(size_t)bc * CH + l] = s[l];
}

// ---------------- G[b,c,l,s] = sum_n C[l,n] B[s,n]  (hoisted) ----------------
__global__ void __launch_bounds__(256) gmat_kernel()
{
    __shared__ float Ct[32][129];
    __shared__ float Bt[32][129];
    const int tid = threadIdx.x;
    const int tx  = tid & 15;
    const int ty  = tid >> 4;
    const int bc  = blockIdx.x;
    const int c   = bc % NC;
    const int b   = bc / NC;
    const int t   = blockIdx.y;
    const int lt  = (t == 0) ? 0 : 1;
    const int st  = (t == 2) ? 1 : 0;
    const size_t rowBase = (size_t)(b * SEQL + c * CH);

    float acc[8][8];
#pragma unroll
    for (int i = 0; i < 8; i++)
#pragma unroll
        for (int j = 0; j < 8; j++) acc[i][j] = 0.f;

    for (int nb = 0; nb < DS; nb += 32) {
        __syncthreads();
#pragma unroll
        for (int it = 0; it < 4; it++) {
            int slot = tid + it * 256;
            int r  = slot >> 3;
            int n4 = (slot & 7) * 4;
            float4 cv = *reinterpret_cast<const float4*>(
                &g_conv[(rowBase + lt * 128 + r) * CONV_DIM + DI + DS + nb + n4]);
            Ct[n4 + 0][r] = cv.x; Ct[n4 + 1][r] = cv.y;
            Ct[n4 + 2][r] = cv.z; Ct[n4 + 3][r] = cv.w;
            float4 bv = *reinterpret_cast<const float4*>(
                &g_conv[(rowBase + st * 128 + r) * CONV_DIM + DI + nb + n4]);
            Bt[n4 + 0][r] = bv.x; Bt[n4 + 1][r] = bv.y;
            Bt[n4 + 2][r] = bv.z; Bt[n4 + 3][r] = bv.w;
        }
        __syncthreads();
#pragma unroll 8
        for (int n = 0; n < 32; n++) {
            float a[8], bb[8];
#pragma unroll
            for (int i = 0; i < 4; i++) {
                a[i]      = Ct[n][ty * 4 + i];
                a[4 + i]  = Ct[n][64 + ty * 4 + i];
                bb[i]     = Bt[n][tx * 4 + i];
                bb[4 + i] = Bt[n][64 + tx * 4 + i];
            }
#pragma unroll
            for (int i = 0; i < 8; i++)
#pragma unroll
                for (int j = 0; j < 8; j++)
                    acc[i][j] = fmaf(a[i], bb[j], acc[i][j]);
        }
    }

    float* Gb = g_G + (size_t)bc * CH * CH;
#pragma unroll
    for (int i = 0; i < 8; i++) {
        int l = lt * 128 + ((i < 4) ? (ty * 4 + i) : (64 + ty * 4 + i - 4));
#pragma unroll
        for (int j = 0; j < 8; j++) {
            int s = st * 128 + ((j < 4) ? (tx * 4 + j) : (64 + tx * 4 + j - 4));
            Gb[(size_t)l * CH + s] = acc[i][j];
        }
    }
}

// ---------------- per-chunk states ----------------
__global__ void __launch_bounds__(256) states_kernel()
{
    __shared__ float Bs[32][129];
    __shared__ float Xs[32][65];
    const int tid = threadIdx.x;
    const int tx  = tid & 15;
    const int ty  = tid >> 4;
    const int h = blockIdx.x % NH;
    const int c = (blockIdx.x / NH) % NC;
    const int b = blockIdx.x / (NH * NC);
    const size_t rowBase = (size_t)(b * SEQL + c * CH);
    const size_t acsBase = ((size_t)(b * NH + h) * NC + c) * CH;
    const float acsLast = g_acs[acsBase + CH - 1];

    float acc[4][8];
#pragma unroll
    for (int i = 0; i < 4; i++)
#pragma unroll
        for (int j = 0; j < 8; j++) acc[i][j] = 0.f;

    for (int s0 = 0; s0 < CH; s0 += 32) {
        __syncthreads();
#pragma unroll
        for (int it = 0; it < 4; it++) {
            int slot = tid + it * 256;
            int sr = slot >> 5;
            int n4 = (slot & 31) * 4;
            float4 v = *reinterpret_cast<const float4*>(
                &g_conv[(rowBase + s0 + sr) * CONV_DIM + DI + n4]);
            Bs[sr][n4 + 0] = v.x; Bs[sr][n4 + 1] = v.y;
            Bs[sr][n4 + 2] = v.z; Bs[sr][n4 + 3] = v.w;
        }
#pragma unroll
        for (int it = 0; it < 2; it++) {
            int slot = tid + it * 256;
            int sr = slot >> 4;
            int p4 = (slot & 15) * 4;
            size_t row = rowBase + s0 + sr;
            float sc = g_dt[row * NH + h] * expf(acsLast - g_acs[acsBase + s0 + sr]);
            float4 v = *reinterpret_cast<const float4*>(&g_conv[row * CONV_DIM + h * HD + p4]);
            Xs[sr][p4 + 0] = v.x * sc; Xs[sr][p4 + 1] = v.y * sc;
            Xs[sr][p4 + 2] = v.z * sc; Xs[sr][p4 + 3] = v.w * sc;
        }
        __syncthreads();
#pragma unroll 8
        for (int s = 0; s < 32; s++) {
            float a[4], bb[8];
#pragma unroll
            for (int i = 0; i < 4; i++) a[i] = Xs[s][ty * 4 + i];
#pragma unroll
            for (int j = 0; j < 4; j++) {
                bb[j]     = Bs[s][tx * 4 + j];
                bb[4 + j] = Bs[s][64 + tx * 4 + j];
            }
#pragma unroll
            for (int i = 0; i < 4; i++)
#pragma unroll
                for (int j = 0; j < 8; j++)
                    acc[i][j] = fmaf(a[i], bb[j], acc[i][j]);
        }
    }
    const size_t base = ((size_t)(b * NC + c) * NH + h) * (HD * DS);
#pragma unroll
    for (int i = 0; i < 4; i++) {
        int p = ty * 4 + i;
#pragma unroll
        for (int j = 0; j < 8; j++) {
            int n = (j < 4) ? (tx * 4 + j) : (64 + tx * 4 + j - 4);
            g_states[base + (size_t)p * DS + n] = acc[i][j];
        }
    }
}

// ---------------- inter-chunk recurrence ----------------
__global__ void chunk_rec_kernel()
{
    int idx = blockIdx.x * blockDim.x + threadIdx.x;
    if (idx >= B_SZ * NH * HD * DS) return;
    int n = idx % DS;
    int p = (idx / DS) % HD;
    int h = (idx / (DS * HD)) % NH;
    int b = idx / (DS * HD * NH);
    float prev = 0.f;
#pragma unroll
    for (int c = 0; c < NC; c++) {
        size_t off = (((size_t)(b * NC + c) * NH + h) * HD + p) * DS + n;
        g_prev[off] = prev;
        float cs = g_acs[((size_t)(b * NH + h) * NC + c) * CH + CH - 1];
        prev = expf(cs) * prev + g_states[off];
    }
}

// ---------------- SSD core (Phase A hoisted) ----------------
struct YS {
    float Cn [DS][129];
    float Pt [32][129];
    float Xd [32][65];
    float Pvn[DS][65];
    float acsl[128];
    float acss[32];
};

__global__ void __launch_bounds__(256) y_kernel(const float* __restrict__ Dvec)
{
    YS& S = *reinterpret_cast<YS*>(dyn_smem);
    const int tid = threadIdx.x;
    const int h  = blockIdx.x % NH;
    const int c  = (blockIdx.x / NH) % NC;
    const int b  = blockIdx.x / (NH * NC);
    const int lt = blockIdx.y;
    const size_t rowBase = (size_t)(b * SEQL + c * CH);
    const size_t acsBase = ((size_t)(b * NH + h) * NC + c) * CH;
    const int ly = tid >> 3;
    const int px = tid & 7;

    const int gl = tid >> 1;
    const int sb = (tid & 1) * 16;
    const float* Gb = g_G + ((size_t)(b * NC + c) * CH + lt * 128 + gl) * CH;

#pragma unroll
    for (int it = 0; it < 16; it++) {
        int slot = tid + it * 256;
        int l  = slot >> 5;
        int n4 = (slot & 31) * 4;
        float4 v = *reinterpret_cast<const float4*>(
            &g_conv[(rowBase + lt * 128 + l) * CONV_DIM + DI + DS + n4]);
        S.Cn[n4 + 0][l] = v.x; S.Cn[n4 + 1][l] = v.y;
        S.Cn[n4 + 2][l] = v.z; S.Cn[n4 + 3][l] = v.w;
    }
    if (tid < 128) S.acsl[tid] = g_acs[acsBase + lt * 128 + tid];
    const size_t pvBase = ((size_t)(b * NC + c) * NH + h) * (HD * DS);
#pragma unroll
    for (int it = 0; it < 8; it++) {
        int slot = tid + it * 256;
        int p  = slot >> 5;
        int n4 = (slot & 31) * 4;
        float4 v = *reinterpret_cast<const float4*>(&g_prev[pvBase + (size_t)p * DS + n4]);
        S.Pvn[n4 + 0][p] = v.x; S.Pvn[n4 + 1][p] = v.y;
        S.Pvn[n4 + 2][p] = v.z; S.Pvn[n4 + 3][p] = v.w;
    }

    float yacc[4][8];
#pragma unroll
    for (int i = 0; i < 4; i++)
#pragma unroll
        for (int j = 0; j < 8; j++) yacc[i][j] = 0.f;

    const int nst = 4 * (lt + 1);
    for (int st = 0; st < nst; st++) {
        const int s0 = st * 32;
        float4 gq[4];
#pragma unroll
        for (int q = 0; q < 4; q++)
            gq[q] = *reinterpret_cast<const float4*>(Gb + s0 + sb + 4 * q);

        __syncthreads();
#pragma unroll
        for (int it = 0; it < 2; it++) {
            int slot = tid + it * 256;
            int sr = slot >> 4;
            int p4 = (slot & 15) * 4;
            size_t row = rowBase + s0 + sr;
            float dt = g_dt[row * NH + h];
            float4 v = *reinterpret_cast<const float4*>(&g_conv[row * CONV_DIM + h * HD + p4]);
            S.Xd[sr][p4 + 0] = v.x * dt; S.Xd[sr][p4 + 1] = v.y * dt;
            S.Xd[sr][p4 + 2] = v.z * dt; S.Xd[sr][p4 + 3] = v.w * dt;
        }
        if (tid < 32) S.acss[tid] = g_acs[acsBase + s0 + tid];
        __syncthreads();

        {
            const int lg = lt * 128 + gl;
            const float al = S.acsl[gl];
            const float* gf = reinterpret_cast<const float*>(gq);
#pragma unroll
            for (int q = 0; q < 16; q++) {
                int sl = sb + q;
                int sg = s0 + sl;
                float w = (sg <= lg) ? expf(al - S.acss[sl]) * gf[q] : 0.f;
                S.Pt[sl][gl] = w;
            }
        }
        __syncthreads();

#pragma unroll 8
        for (int s = 0; s < 32; s++) {
            float a[4], bb[8];
#pragma unroll
            for (int i = 0; i < 4; i++) a[i] = S.Pt[s][ly * 4 + i];
#pragma unroll
            for (int j = 0; j < 4; j++) {
                bb[j]     = S.Xd[s][px * 4 + j];
                bb[4 + j] = S.Xd[s][32 + px * 4 + j];
            }
#pragma unroll
            for (int i = 0; i < 4; i++)
#pragma unroll
                for (int j = 0; j < 8; j++)
                    yacc[i][j] = fmaf(a[i], bb[j], yacc[i][j]);
        }
    }

    float oacc[4][8];
#pragma unroll
    for (int i = 0; i < 4; i++)
#pragma unroll
        for (int j = 0; j < 8; j++) oacc[i][j] = 0.f;
#pragma unroll 4
    for (int n = 0; n < DS; n++) {
        float a[4], bb[8];
#pragma unroll
        for (int i = 0; i < 4; i++) a[i] = S.Cn[n][ly * 4 + i];
#pragma unroll
        for (int j = 0; j < 4; j++) {
            bb[j]     = S.Pvn[n][px * 4 + j];
            bb[4 + j] = S.Pvn[n][32 + px * 4 + j];
        }
#pragma unroll
        for (int i = 0; i < 4; i++)
#pragma unroll
            for (int j = 0; j < 8; j++)
                oacc[i][j] = fmaf(a[i], bb[j], oacc[i][j]);
    }

    const float Dh = Dvec[h];
#pragma unroll
    for (int i = 0; i < 4; i++) {
        int l = ly * 4 + i;
        size_t row = rowBase + lt * 128 + l;
        float el = expf(S.acsl[l]);
#pragma unroll
        for (int j = 0; j < 8; j++) {
            int p = (j < 4) ? (px * 4 + j) : (32 + px * 4 + j - 4);
            float xs = g_conv[row * CONV_DIM + h * HD + p];
            g_y[row * DI + h * HD + p] = yacc[i][j] + el * oacc[i][j] + Dh * xs;
        }
    }
}

// ---------------- gate with silu(z) + RMSNorm ----------------
__global__ void __launch_bounds__(256) gate_norm_kernel(const float* __restrict__ norm_w)
{
    const int row = blockIdx.x;
    const float* yrow = &g_y[(size_t)row * DI];
    const float* zrow = &g_zxbcdt[(size_t)row * DPROJ];
    float vals[16];
    float ss = 0.f;
#pragma unroll
    for (int it = 0; it < 16; it++) {
        int i = threadIdx.x + it * 256;
        float z  = zrow[i];
        float yg = yrow[i] * (z / (1.f + expf(-z)));
        vals[it] = yg;
        ss = fmaf(yg, yg, ss);
    }
    __shared__ float red[8];
#pragma unroll
    for (int o = 16; o > 0; o >>= 1) ss += __shfl_xor_sync(0xffffffffu, ss, o);
    if ((threadIdx.x & 31) == 0) red[threadIdx.x >> 5] = ss;
    __syncthreads();
    float tot = 0.f;
#pragma unroll
    for (int w = 0; w < 8; w++) tot += red[w];
    float scale = rsqrtf(tot / (float)DI + EPSV);
    float* yw = &g_y[(size_t)row * DI];
#pragma unroll
    for (int it = 0; it < 16; it++) {
        int i = threadIdx.x + it * 256;
        yw[i] = vals[it] * scale * norm_w[i];
    }
}

// ---------------- launch ----------------
extern "C" void kernel_launch(void* const* d_in, const int* in_sizes, int n_in,
                              void* d_out, int out_size)
{
    (void)in_sizes; (void)n_in; (void)out_size;
    const float* x        = (const float*)d_in[0];
    const float* in_proj  = (const float*)d_in[1];
    const float* conv_w   = (const float*)d_in[2];
    const float* conv_b   = (const float*)d_in[3];
    const float* dt_bias  = (const float*)d_in[4];
    const float* A_log    = (const float*)d_in[5];
    const float* Dv       = (const float*)d_in[6];
    const float* norm_w   = (const float*)d_in[7];
    const float* out_proj = (const float*)d_in[8];
    float* out = (float*)d_out;

    float* zx = nullptr;
    float* yb = nullptr;
    cudaGetSymbolAddress((void**)&zx, g_zxbcdt);
    cudaGetSymbolAddress((void**)&yb, g_y);

    cudaFuncSetAttribute(y_kernel, cudaFuncAttributeMaxDynamicSharedMemorySize,
                         (int)sizeof(YS));
    cudaFuncSetAttribute(gemm_bf16x3_tn, cudaFuncAttributeMaxDynamicSharedMemorySize,
                         GEMM_SMEM);

    // 1. in_proj GEMM (bf16x3, 4-stage pipeline, 1 sync / 2 steps)
    gemm_bf16x3_tn<<<dim3((DPROJ + 127) / 128, BL / 128), 256, GEMM_SMEM>>>(
        x, in_proj, zx, BL, DPROJ, DM);
    // 2. depthwise conv + silu
    conv_silu_kernel<<<(BL * CONV_DIM + 255) / 256, 256>>>(conv_w, conv_b);
    // 3. dt = softplus
    dt_kernel<<<(BL * NH + 255) / 256, 256>>>(dt_bias);
    // 4. per-chunk cumsum of dA
    scan_kernel<<<B_SZ * NH * NC, CH>>>(A_log);
    // 5. G = C·B^T per (b,c)
    gmat_kernel<<<dim3(B_SZ * NC, 3), 256>>>();
    // 6. per-chunk states
    states_kernel<<<B_SZ * NC * NH, 256>>>();
    // 7. inter-chunk recurrence
    chunk_rec_kernel<<<(B_SZ * NH * HD * DS + 255) / 256, 256>>>();
    // 8. SSD core -> Y
    y_kernel<<<dim3(B_SZ * NC * NH, 2), 256, sizeof(YS)>>>(Dv);
    // 9. gate + RMSNorm
    gate_norm_kernel<<<BL, 256>>>(norm_w);
    // 10. out_proj GEMM (bf16x3, 4-stage pipeline, 1 sync / 2 steps)
    gemm_bf16x3_tn<<<dim3(DM / 128, BL / 128), 256, GEMM_SMEM>>>(
        yb, out_proj, out, BL, DM, DI);
}